// round 1
// baseline (speedup 1.0000x reference)
#include <cuda_runtime.h>
#include <cuda_bf16.h>
#include <math.h>

// Problem constants
#define D_INC   2048
#define D_OUTC  2048
#define NHEADS  16
#define HDIM    128
#define LATENT  256
#define BATCH   2
#define SEQ     2048
#define MTOT    (BATCH * SEQ)        // 4096

// ---------------------------------------------------------------------------
// Scratch (device globals; no allocation allowed)
// ---------------------------------------------------------------------------
__device__ float g_q  [(size_t)MTOT * D_OUTC];        // 32 MB
__device__ float g_lat[(size_t)MTOT * LATENT];        //  4 MB
__device__ float g_kv [(size_t)MTOT * 2 * D_OUTC];    // 64 MB  (k | v)
__device__ float g_ctx[(size_t)MTOT * D_OUTC];        // 32 MB

// ---------------------------------------------------------------------------
// Generic fp32 GEMM: C[M,N] = A[M,K] @ B[K,N] (+ bias), all row-major.
// Tiles: BM=BN=128, BK=16. 256 threads, 8x8 microtile per thread (contiguous
// mapping -> float4 LDS, conflict-free).
// Requires M%128==0, N%128==0, K%16==0 (true for all shapes here).
// ---------------------------------------------------------------------------
__global__ __launch_bounds__(256, 2)
void gemm_kernel(const float* __restrict__ A, const float* __restrict__ Bm,
                 const float* __restrict__ bias, float* __restrict__ C,
                 int M, int N, int K)
{
    __shared__ float As[16][128];   // transposed A tile: As[k][m]
    __shared__ float Bs[16][128];   // Bs[k][n]

    const int tid = threadIdx.x;
    const int tx = tid & 15;        // 0..15 -> N
    const int ty = tid >> 4;        // 0..15 -> M
    const int m0 = blockIdx.y * 128;
    const int n0 = blockIdx.x * 128;

    float acc[8][8];
#pragma unroll
    for (int i = 0; i < 8; i++)
#pragma unroll
        for (int j = 0; j < 8; j++) acc[i][j] = 0.f;

    for (int k0 = 0; k0 < K; k0 += 16) {
        // Load A tile 128x16 (512 float4, 2 per thread), store transposed
#pragma unroll
        for (int it = 0; it < 2; it++) {
            int f   = tid + it * 256;          // 0..511
            int row = f >> 2;                  // 0..127
            int c4  = (f & 3) * 4;             // 0,4,8,12
            float4 v = *reinterpret_cast<const float4*>(
                &A[(size_t)(m0 + row) * K + k0 + c4]);
            As[c4 + 0][row] = v.x;
            As[c4 + 1][row] = v.y;
            As[c4 + 2][row] = v.z;
            As[c4 + 3][row] = v.w;
        }
        // Load B tile 16x128 (512 float4, 2 per thread)
#pragma unroll
        for (int it = 0; it < 2; it++) {
            int f   = tid + it * 256;
            int row = f >> 5;                  // 0..15
            int col = (f & 31) * 4;            // 0..124
            *reinterpret_cast<float4*>(&Bs[row][col]) =
                *reinterpret_cast<const float4*>(
                    &Bm[(size_t)(k0 + row) * N + n0 + col]);
        }
        __syncthreads();

#pragma unroll
        for (int kk = 0; kk < 16; kk++) {
            float a[8], b[8];
            float4 a0 = *reinterpret_cast<const float4*>(&As[kk][ty * 8]);
            float4 a1 = *reinterpret_cast<const float4*>(&As[kk][ty * 8 + 4]);
            float4 b0 = *reinterpret_cast<const float4*>(&Bs[kk][tx * 8]);
            float4 b1 = *reinterpret_cast<const float4*>(&Bs[kk][tx * 8 + 4]);
            a[0]=a0.x; a[1]=a0.y; a[2]=a0.z; a[3]=a0.w;
            a[4]=a1.x; a[5]=a1.y; a[6]=a1.z; a[7]=a1.w;
            b[0]=b0.x; b[1]=b0.y; b[2]=b0.z; b[3]=b0.w;
            b[4]=b1.x; b[5]=b1.y; b[6]=b1.z; b[7]=b1.w;
#pragma unroll
            for (int i = 0; i < 8; i++)
#pragma unroll
                for (int j = 0; j < 8; j++)
                    acc[i][j] = fmaf(a[i], b[j], acc[i][j]);
        }
        __syncthreads();
    }

    // Epilogue (optionally add bias)
    float bv[8];
    if (bias) {
#pragma unroll
        for (int j = 0; j < 8; j++) bv[j] = bias[n0 + tx * 8 + j];
    } else {
#pragma unroll
        for (int j = 0; j < 8; j++) bv[j] = 0.f;
    }
#pragma unroll
    for (int i = 0; i < 8; i++) {
        size_t rowoff = (size_t)(m0 + ty * 8 + i) * N + n0 + tx * 8;
        float4 w0, w1;
        w0.x = acc[i][0] + bv[0]; w0.y = acc[i][1] + bv[1];
        w0.z = acc[i][2] + bv[2]; w0.w = acc[i][3] + bv[3];
        w1.x = acc[i][4] + bv[4]; w1.y = acc[i][5] + bv[5];
        w1.z = acc[i][6] + bv[6]; w1.w = acc[i][7] + bv[7];
        *reinterpret_cast<float4*>(&C[rowoff])     = w0;
        *reinterpret_cast<float4*>(&C[rowoff + 4]) = w1;
    }
}

// ---------------------------------------------------------------------------
// Fused flash attention (fp32, causal), per (b,h): BQ=BK=128, hd=128.
// 256 threads, interleaved (stride-16) 8x8 microtiles so scalar LDS are
// conflict-free with odd row stride. P reuses the K smem buffer.
// smem: 3 * 128 * 129 * 4 = 198144 B (dynamic, opt-in).
// ---------------------------------------------------------------------------
#define ASTR 129
#define ATTN_SMEM (3 * 128 * ASTR * 4)

__global__ __launch_bounds__(256, 1)
void attn_kernel(const float* __restrict__ Q, const float* __restrict__ KV,
                 float* __restrict__ Ctx)
{
    extern __shared__ float sm[];
    float* Qs = sm;                   // [128][ASTR]
    float* Ks = sm + 128 * ASTR;      // [128][ASTR], reused for P
    float* Vs = sm + 2 * 128 * ASTR;  // [128][ASTR]

    const int tid = threadIdx.x;
    const int tx = tid & 15;          // key-col group / hd-col group
    const int ty = tid >> 4;          // q-row group
    const int qb = blockIdx.x;        // q tile index (0..15)
    const int h  = blockIdx.y;
    const int b  = blockIdx.z;

    const float inv_sqrt = rsqrtf((float)HDIM);

    const size_t qbase  = (size_t)b * SEQ * D_OUTC + (size_t)h * HDIM;
    const size_t kvbase = (size_t)b * SEQ * (2 * D_OUTC) + (size_t)h * HDIM;

    // Load Q tile [128 x 128]
#pragma unroll
    for (int it = 0; it < 16; it++) {
        int f   = tid + it * 256;        // 0..4095 float4
        int row = f >> 5;                // 0..127
        int col = (f & 31) * 4;          // 0..124
        float4 v = *reinterpret_cast<const float4*>(
            &Q[qbase + (size_t)(qb * 128 + row) * D_OUTC + col]);
        float* dst = &Qs[row * ASTR + col];
        dst[0] = v.x; dst[1] = v.y; dst[2] = v.z; dst[3] = v.w;
    }

    float o[8][8];
    float mrow[8], lrow[8];
#pragma unroll
    for (int i = 0; i < 8; i++) {
        mrow[i] = -INFINITY; lrow[i] = 0.f;
#pragma unroll
        for (int d = 0; d < 8; d++) o[i][d] = 0.f;
    }

    for (int kb = 0; kb <= qb; kb++) {
        __syncthreads();   // previous P@V readers done before overwrite
        // Load K and V tiles [128 x 128]
#pragma unroll
        for (int it = 0; it < 16; it++) {
            int f   = tid + it * 256;
            int row = f >> 5;
            int col = (f & 31) * 4;
            size_t goff = kvbase + (size_t)(kb * 128 + row) * (2 * D_OUTC) + col;
            float4 kv4 = *reinterpret_cast<const float4*>(&KV[goff]);
            float4 vv4 = *reinterpret_cast<const float4*>(&KV[goff + D_OUTC]);
            float* kd = &Ks[row * ASTR + col];
            float* vd = &Vs[row * ASTR + col];
            kd[0] = kv4.x; kd[1] = kv4.y; kd[2] = kv4.z; kd[3] = kv4.w;
            vd[0] = vv4.x; vd[1] = vv4.y; vd[2] = vv4.z; vd[3] = vv4.w;
        }
        __syncthreads();

        // S = Q @ K^T  (rows i = ty + ii*16, cols j = tx + jj*16)
        float s[8][8];
#pragma unroll
        for (int i = 0; i < 8; i++)
#pragma unroll
            for (int j = 0; j < 8; j++) s[i][j] = 0.f;

#pragma unroll 4
        for (int d = 0; d < HDIM; d++) {
            float a[8], bb[8];
#pragma unroll
            for (int i = 0; i < 8; i++) a[i]  = Qs[(ty + i * 16) * ASTR + d];
#pragma unroll
            for (int j = 0; j < 8; j++) bb[j] = Ks[(tx + j * 16) * ASTR + d];
#pragma unroll
            for (int i = 0; i < 8; i++)
#pragma unroll
                for (int j = 0; j < 8; j++)
                    s[i][j] = fmaf(a[i], bb[j], s[i][j]);
        }

        // Scale + causal mask (mask->-inf is scale-invariant, matches ref)
        const bool diag = (kb == qb);
#pragma unroll
        for (int i = 0; i < 8; i++) {
            int rloc = ty + i * 16;
#pragma unroll
            for (int j = 0; j < 8; j++) {
                int cloc = tx + j * 16;
                float sv = s[i][j] * inv_sqrt;
                if (diag && cloc > rloc) sv = -INFINITY;
                s[i][j] = sv;
            }
        }

        // Online softmax: rows are shared by the 16 lanes with equal ty
        // (contiguous 16-lane halves of each warp -> shfl width 16).
#pragma unroll
        for (int i = 0; i < 8; i++) {
            float mloc = s[i][0];
#pragma unroll
            for (int j = 1; j < 8; j++) mloc = fmaxf(mloc, s[i][j]);
#pragma unroll
            for (int w = 1; w < 16; w <<= 1)
                mloc = fmaxf(mloc, __shfl_xor_sync(0xffffffffu, mloc, w));
            float mnew = fmaxf(mrow[i], mloc);
            float corr = __expf(mrow[i] - mnew);
            mrow[i] = mnew;
            float lloc = 0.f;
#pragma unroll
            for (int j = 0; j < 8; j++) {
                float p = __expf(s[i][j] - mnew);
                s[i][j] = p;
                lloc += p;
            }
#pragma unroll
            for (int w = 1; w < 16; w <<= 1)
                lloc += __shfl_xor_sync(0xffffffffu, lloc, w);
            lrow[i] = lrow[i] * corr + lloc;
#pragma unroll
            for (int d = 0; d < 8; d++) o[i][d] *= corr;
        }

        __syncthreads();   // all S-readers of Ks done
        // Write P into Ks
#pragma unroll
        for (int i = 0; i < 8; i++)
#pragma unroll
            for (int j = 0; j < 8; j++)
                Ks[(ty + i * 16) * ASTR + tx + j * 16] = s[i][j];
        __syncthreads();

        // O += P @ V   (O cols d = tx + dd*16)
#pragma unroll 4
        for (int j = 0; j < 128; j++) {
            float a8[8], b8[8];
#pragma unroll
            for (int i = 0; i < 8; i++)  a8[i] = Ks[(ty + i * 16) * ASTR + j];
#pragma unroll
            for (int d = 0; d < 8; d++)  b8[d] = Vs[j * ASTR + tx + d * 16];
#pragma unroll
            for (int i = 0; i < 8; i++)
#pragma unroll
                for (int d = 0; d < 8; d++)
                    o[i][d] = fmaf(a8[i], b8[d], o[i][d]);
        }
    }

    // Normalize and write ctx
#pragma unroll
    for (int i = 0; i < 8; i++) {
        float inv_l = 1.f / lrow[i];
        size_t rowoff = (size_t)(b * SEQ + qb * 128 + ty + i * 16) * D_OUTC
                        + (size_t)h * HDIM + tx;
#pragma unroll
        for (int d = 0; d < 8; d++)
            Ctx[rowoff + d * 16] = o[i][d] * inv_l;
    }
}

// ---------------------------------------------------------------------------
// Launch
// ---------------------------------------------------------------------------
extern "C" void kernel_launch(void* const* d_in, const int* in_sizes, int n_in,
                              void* d_out, int out_size)
{
    const float* x     = (const float*)d_in[0];
    const float* Wq    = (const float*)d_in[1];
    const float* Wdkv  = (const float*)d_in[2];
    const float* Wukv  = (const float*)d_in[3];
    const float* Wout  = (const float*)d_in[4];
    const float* bout  = (const float*)d_in[5];
    float* out = (float*)d_out;

    float *q, *lat, *kv, *ctx;
    cudaGetSymbolAddress((void**)&q,   g_q);
    cudaGetSymbolAddress((void**)&lat, g_lat);
    cudaGetSymbolAddress((void**)&kv,  g_kv);
    cudaGetSymbolAddress((void**)&ctx, g_ctx);

    cudaFuncSetAttribute(attn_kernel,
                         cudaFuncAttributeMaxDynamicSharedMemorySize,
                         ATTN_SMEM);

    dim3 blk(256);

    // 1) q = x @ Wq                [4096,2048] x [2048,2048]
    gemm_kernel<<<dim3(D_OUTC / 128, MTOT / 128), blk>>>(
        x, Wq, nullptr, q, MTOT, D_OUTC, D_INC);

    // 2) latent = x @ Wdkv         [4096,2048] x [2048,256]
    gemm_kernel<<<dim3(LATENT / 128, MTOT / 128), blk>>>(
        x, Wdkv, nullptr, lat, MTOT, LATENT, D_INC);

    // 3) kv = latent @ Wukv        [4096,256] x [256,4096]
    gemm_kernel<<<dim3((2 * D_OUTC) / 128, MTOT / 128), blk>>>(
        lat, Wukv, nullptr, kv, MTOT, 2 * D_OUTC, LATENT);

    // 4) attention -> ctx
    attn_kernel<<<dim3(SEQ / 128, NHEADS, BATCH), blk, ATTN_SMEM>>>(
        q, kv, ctx);

    // 5) out = ctx @ Wout + b
    gemm_kernel<<<dim3(D_INC / 128, MTOT / 128), blk>>>(
        ctx, Wout, bout, out, MTOT, D_INC, D_OUTC);
}

// round 3
// speedup vs baseline: 7.4115x; 7.4115x over previous
#include <cuda_runtime.h>
#include <cuda_fp16.h>
#include <cstdint>
#include <math.h>

// Problem constants
#define D_INC   2048
#define D_OUTC  2048
#define NHEADS  16
#define HDIM    128
#define LATENT  256
#define BATCH   2
#define SEQ     2048
#define MTOT    (BATCH * SEQ)        // 4096

#define NEG_BIG (-1.0e30f)

// ---------------------------------------------------------------------------
// Scratch (device globals; no allocation allowed)
// ---------------------------------------------------------------------------
__device__ __align__(16) __half g_xh  [(size_t)MTOT * D_INC];
__device__ __align__(16) __half g_qh  [(size_t)MTOT * D_OUTC];
__device__ __align__(16) __half g_lath[(size_t)MTOT * LATENT];
__device__ __align__(16) __half g_kvh [(size_t)MTOT * 2 * D_OUTC];
__device__ __align__(16) __half g_ctxh[(size_t)MTOT * D_OUTC];
__device__ __align__(16) __half g_wqT  [(size_t)D_OUTC * D_INC];
__device__ __align__(16) __half g_wdkvT[(size_t)LATENT * D_INC];
__device__ __align__(16) __half g_wukvT[(size_t)(2 * D_OUTC) * LATENT];
__device__ __align__(16) __half g_woutT[(size_t)D_INC * D_OUTC];

// ---------------------------------------------------------------------------
// PTX helpers (legacy tensor path: ldmatrix + mma.sync, cp.async)
// ---------------------------------------------------------------------------
__device__ __forceinline__ uint32_t smem_u32(const void* p) {
    uint32_t a;
    asm("{ .reg .u64 t; cvta.to.shared.u64 t, %1; cvt.u32.u64 %0, t; }"
        : "=r"(a) : "l"(p));
    return a;
}

#define CP_ASYNC16(dst, src) \
    asm volatile("cp.async.cg.shared.global [%0], [%1], 16;" \
                 :: "r"(dst), "l"(src) : "memory")
#define CP_COMMIT() asm volatile("cp.async.commit_group;" ::: "memory")
#define CP_WAIT1()  asm volatile("cp.async.wait_group 1;" ::: "memory")
#define CP_WAIT0()  asm volatile("cp.async.wait_group 0;" ::: "memory")

#define LDSM_X4(r0, r1, r2, r3, a) \
    asm volatile("ldmatrix.sync.aligned.m8n8.x4.shared.b16 {%0,%1,%2,%3}, [%4];" \
                 : "=r"(r0), "=r"(r1), "=r"(r2), "=r"(r3) : "r"(a))
#define LDSM_X4_T(r0, r1, r2, r3, a) \
    asm volatile("ldmatrix.sync.aligned.m8n8.x4.trans.shared.b16 {%0,%1,%2,%3}, [%4];" \
                 : "=r"(r0), "=r"(r1), "=r"(r2), "=r"(r3) : "r"(a))

// D(fp32x4) += A(fp16 4reg) * B(fp16 2reg)
#define MMA16816(d, a, b0_, b1_) \
    asm volatile("mma.sync.aligned.m16n8k16.row.col.f32.f16.f16.f32 " \
                 "{%0,%1,%2,%3}, {%4,%5,%6,%7}, {%8,%9}, {%0,%1,%2,%3};" \
                 : "+f"((d)[0]), "+f"((d)[1]), "+f"((d)[2]), "+f"((d)[3]) \
                 : "r"((a)[0]), "r"((a)[1]), "r"((a)[2]), "r"((a)[3]), \
                   "r"(b0_), "r"(b1_))

// XOR swizzles: tile rows of 128B (8 chunks) / 256B (16 chunks), 16B chunks
__device__ __forceinline__ uint32_t swz128(uint32_t r, uint32_t c) {
    return r * 128u + ((c ^ (r & 7u)) << 4);
}
__device__ __forceinline__ uint32_t swz256(uint32_t r, uint32_t c) {
    return r * 256u + ((c ^ (r & 7u)) << 4);
}

__device__ __forceinline__ uint32_t packh2(float a, float b) {
    __half2 h = __floats2half2_rn(a, b);
    return *reinterpret_cast<uint32_t*>(&h);
}

// ---------------------------------------------------------------------------
// fp16 GEMM via mma.sync: C[M,N] = A[M,K] @ Bt[N,K]^T (+bias)
// CTA 128x128, BK=64, 8 warps (2M x 4N), warp tile 64x32. Double buffered.
// smem per stage: A 16KB + B 16KB; two stages = 64KB.
// ---------------------------------------------------------------------------
#define GEMM_SMEM (65536 + 1024)

__device__ __forceinline__ void gemm_load_stage(
    uint32_t bufA, uint32_t bufB,
    const __half* __restrict__ A, const __half* __restrict__ Bt,
    int lda, int ldb, int m0, int n0, int k0, int tid)
{
#pragma unroll
    for (int i = 0; i < 4; i++) {            // A: 128 rows x 8 chunks
        int f = tid + i * 256;
        int r = f >> 3, c = f & 7;
        CP_ASYNC16(bufA + swz128(r, c),
                   A + (size_t)(m0 + r) * lda + k0 + c * 8);
    }
#pragma unroll
    for (int i = 0; i < 4; i++) {            // B: 128 rows x 8 chunks
        int f = tid + i * 256;
        int r = f >> 3, c = f & 7;
        CP_ASYNC16(bufB + swz128(r, c),
                   Bt + (size_t)(n0 + r) * ldb + k0 + c * 8);
    }
}

__global__ __launch_bounds__(256, 2)
void gemm_h_kernel(const __half* __restrict__ A, const __half* __restrict__ Bt,
                   const float* __restrict__ bias, void* __restrict__ Cv,
                   int M, int N, int K, int lda, int ldb, int ldc, int halfout)
{
    extern __shared__ char smem_raw[];
    uint32_t sb = (smem_u32(smem_raw) + 1023u) & ~1023u;

    const int tid  = threadIdx.x;
    const int wid  = tid >> 5;
    const int lane = tid & 31;
    const int wm   = wid & 1;        // 0..1 (64 rows each)
    const int wn   = wid >> 1;       // 0..3 (32 cols each)
    const int g    = lane >> 2;
    const int tig  = lane & 3;
    const int m0 = blockIdx.y * 128;
    const int n0 = blockIdx.x * 128;

    float acc[4][4][4];
#pragma unroll
    for (int mt = 0; mt < 4; mt++)
#pragma unroll
        for (int nt = 0; nt < 4; nt++)
#pragma unroll
            for (int e = 0; e < 4; e++) acc[mt][nt][e] = 0.f;

    const int S = K >> 6;

    gemm_load_stage(sb, sb + 16384, A, Bt, lda, ldb, m0, n0, 0, tid);
    CP_COMMIT();
    gemm_load_stage(sb + 32768, sb + 49152, A, Bt, lda, ldb, m0, n0, 64, tid);
    CP_COMMIT();

    for (int s = 0; s < S; s++) {
        CP_WAIT1();
        __syncthreads();
        const uint32_t bA = sb + (s & 1) * 32768;
        const uint32_t bB = bA + 16384;

#pragma unroll
        for (int kt = 0; kt < 4; kt++) {
            uint32_t af[4][4];
#pragma unroll
            for (int mt = 0; mt < 4; mt++) {
                uint32_t row = wm * 64 + mt * 16 + (lane & 15);
                uint32_t ch  = kt * 2 + (lane >> 4);
                LDSM_X4(af[mt][0], af[mt][1], af[mt][2], af[mt][3],
                        bA + swz128(row, ch));
            }
            uint32_t bf[4][2];
#pragma unroll
            for (int np = 0; np < 2; np++) {
                uint32_t row = wn * 32 + np * 16 + ((lane >> 4) << 3) + (lane & 7);
                uint32_t ch  = kt * 2 + ((lane >> 3) & 1);
                uint32_t r0, r1, r2, r3;
                LDSM_X4(r0, r1, r2, r3, bB + swz128(row, ch));
                bf[2 * np][0] = r0; bf[2 * np][1] = r1;
                bf[2 * np + 1][0] = r2; bf[2 * np + 1][1] = r3;
            }
#pragma unroll
            for (int mt = 0; mt < 4; mt++)
#pragma unroll
                for (int nt = 0; nt < 4; nt++)
                    MMA16816(acc[mt][nt], af[mt], bf[nt][0], bf[nt][1]);
        }
        __syncthreads();
        if (s + 2 < S)
            gemm_load_stage(bA, bB, A, Bt, lda, ldb, m0, n0, (s + 2) * 64, tid);
        CP_COMMIT();
    }

    // Epilogue
#pragma unroll
    for (int mt = 0; mt < 4; mt++) {
#pragma unroll
        for (int nt = 0; nt < 4; nt++) {
            int row = m0 + wm * 64 + mt * 16 + g;
            int col = n0 + wn * 32 + nt * 8 + 2 * tig;
            float* a = acc[mt][nt];
            if (halfout) {
                __half* C = (__half*)Cv;
                *(uint32_t*)(C + (size_t)row * ldc + col)       = packh2(a[0], a[1]);
                *(uint32_t*)(C + (size_t)(row + 8) * ldc + col) = packh2(a[2], a[3]);
            } else {
                float* C = (float*)Cv;
                float b0 = bias ? bias[col]     : 0.f;
                float b1 = bias ? bias[col + 1] : 0.f;
                float2 v0 = make_float2(a[0] + b0, a[1] + b1);
                float2 v1 = make_float2(a[2] + b0, a[3] + b1);
                *(float2*)(C + (size_t)row * ldc + col)       = v0;
                *(float2*)(C + (size_t)(row + 8) * ldc + col) = v1;
            }
        }
    }
}

// ---------------------------------------------------------------------------
// Flash attention, fp16 mma.sync, causal. BQ=128, BK=64, 8 warps x 16 rows.
// smem: Q 32KB + 2 stages of (K 16KB + V 16KB) = 96KB.
// ---------------------------------------------------------------------------
#define ATTN_SMEM (98304 + 1024)

__global__ __launch_bounds__(256, 1)
void attn_h_kernel(const __half* __restrict__ qh, const __half* __restrict__ kvh,
                   __half* __restrict__ ctxh)
{
    extern __shared__ char smem_raw[];
    uint32_t sb = (smem_u32(smem_raw) + 1023u) & ~1023u;
    const uint32_t Qs = sb;                  // [128][128] h, 256B rows
    const uint32_t KV0 = sb + 32768;         // stage0: K 16KB, V 16KB
    const uint32_t KV1 = sb + 65536;         // stage1

    const int tid  = threadIdx.x;
    const int wq   = tid >> 5;               // warp -> 16 q rows
    const int lane = tid & 31;
    const int g    = lane >> 2;
    const int tig  = lane & 3;
    const int qb = blockIdx.x;
    const int h  = blockIdx.y;
    const int b  = blockIdx.z;

    const int qrow0 = qb * 128;
    const size_t qrowg  = (size_t)b * SEQ + qrow0;
    const size_t kvrowg = (size_t)b * SEQ;
    const float SCALE = 0.08838834764831845f;   // rsqrt(128)

    // Q tile load (group with stage0)
#pragma unroll
    for (int i = 0; i < 8; i++) {
        int f = tid + i * 256;
        int r = f >> 4, c = f & 15;
        CP_ASYNC16(Qs + swz256(r, c),
                   qh + (qrowg + r) * D_OUTC + h * HDIM + c * 8);
    }
    // K/V stage 0
    {
#pragma unroll
        for (int i = 0; i < 4; i++) {
            int f = tid + i * 256;
            int r = f >> 4, c = f & 15;
            const __half* src = kvh + (kvrowg + r) * (2 * D_OUTC) + h * HDIM + c * 8;
            CP_ASYNC16(KV0 + swz256(r, c), src);                    // K
            CP_ASYNC16(KV0 + 16384 + swz256(r, c), src + D_OUTC);   // V
        }
    }
    CP_COMMIT();

    const int KB = 2 * qb + 2;

    float ob[16][4];
#pragma unroll
    for (int nt = 0; nt < 16; nt++)
#pragma unroll
        for (int e = 0; e < 4; e++) ob[nt][e] = 0.f;
    float mA = NEG_BIG, mB = NEG_BIG, lA = 0.f, lB = 0.f;
    uint32_t qf[8][4];
    const int grA = qrow0 + wq * 16 + g;
    const int grB = grA + 8;

    for (int kb = 0; kb < KB; kb++) {
        // prefetch next stage
        if (kb + 1 < KB) {
            uint32_t nb = ((kb + 1) & 1) ? KV1 : KV0;
#pragma unroll
            for (int i = 0; i < 4; i++) {
                int f = tid + i * 256;
                int r = f >> 4, c = f & 15;
                const __half* src = kvh + (kvrowg + (size_t)(kb + 1) * 64 + r) * (2 * D_OUTC)
                                    + h * HDIM + c * 8;
                CP_ASYNC16(nb + swz256(r, c), src);
                CP_ASYNC16(nb + 16384 + swz256(r, c), src + D_OUTC);
            }
        }
        CP_COMMIT();
        CP_WAIT1();
        __syncthreads();

        if (kb == 0) {
#pragma unroll
            for (int kt = 0; kt < 8; kt++) {
                uint32_t row = wq * 16 + (lane & 15);
                uint32_t ch  = kt * 2 + (lane >> 4);
                LDSM_X4(qf[kt][0], qf[kt][1], qf[kt][2], qf[kt][3],
                        Qs + swz256(row, ch));
            }
        }

        const uint32_t Kbuf = (kb & 1) ? KV1 : KV0;
        const uint32_t Vbuf = Kbuf + 16384;

        // S = Q @ K^T
        float sc[8][4];
#pragma unroll
        for (int nt = 0; nt < 8; nt++)
#pragma unroll
            for (int e = 0; e < 4; e++) sc[nt][e] = 0.f;

#pragma unroll
        for (int np = 0; np < 4; np++) {
#pragma unroll
            for (int kt = 0; kt < 8; kt++) {
                uint32_t row = np * 16 + ((lane >> 4) << 3) + (lane & 7);
                uint32_t ch  = kt * 2 + ((lane >> 3) & 1);
                uint32_t r0, r1, r2, r3;
                LDSM_X4(r0, r1, r2, r3, Kbuf + swz256(row, ch));
                MMA16816(sc[2 * np],     qf[kt], r0, r1);
                MMA16816(sc[2 * np + 1], qf[kt], r2, r3);
            }
        }

        // scale + causal mask
        const bool need_mask = (kb >= 2 * qb);
#pragma unroll
        for (int nt = 0; nt < 8; nt++) {
            int c0 = kb * 64 + nt * 8 + 2 * tig;
            sc[nt][0] *= SCALE; sc[nt][1] *= SCALE;
            sc[nt][2] *= SCALE; sc[nt][3] *= SCALE;
            if (need_mask) {
                if (c0     > grA) sc[nt][0] = NEG_BIG;
                if (c0 + 1 > grA) sc[nt][1] = NEG_BIG;
                if (c0     > grB) sc[nt][2] = NEG_BIG;
                if (c0 + 1 > grB) sc[nt][3] = NEG_BIG;
            }
        }

        // online softmax (rows g, g+8); quad reduce over tig
        float mAn = NEG_BIG, mBn = NEG_BIG;
#pragma unroll
        for (int nt = 0; nt < 8; nt++) {
            mAn = fmaxf(mAn, fmaxf(sc[nt][0], sc[nt][1]));
            mBn = fmaxf(mBn, fmaxf(sc[nt][2], sc[nt][3]));
        }
        mAn = fmaxf(mAn, __shfl_xor_sync(0xffffffffu, mAn, 1));
        mAn = fmaxf(mAn, __shfl_xor_sync(0xffffffffu, mAn, 2));
        mBn = fmaxf(mBn, __shfl_xor_sync(0xffffffffu, mBn, 1));
        mBn = fmaxf(mBn, __shfl_xor_sync(0xffffffffu, mBn, 2));
        float mAnew = fmaxf(mA, mAn);
        float mBnew = fmaxf(mB, mBn);
        float corrA = __expf(mA - mAnew);
        float corrB = __expf(mB - mBnew);
        mA = mAnew; mB = mBnew;

        float lAs = 0.f, lBs = 0.f;
#pragma unroll
        for (int nt = 0; nt < 8; nt++) {
            sc[nt][0] = __expf(sc[nt][0] - mA);
            sc[nt][1] = __expf(sc[nt][1] - mA);
            sc[nt][2] = __expf(sc[nt][2] - mB);
            sc[nt][3] = __expf(sc[nt][3] - mB);
            lAs += sc[nt][0] + sc[nt][1];
            lBs += sc[nt][2] + sc[nt][3];
        }
        lAs += __shfl_xor_sync(0xffffffffu, lAs, 1);
        lAs += __shfl_xor_sync(0xffffffffu, lAs, 2);
        lBs += __shfl_xor_sync(0xffffffffu, lBs, 1);
        lBs += __shfl_xor_sync(0xffffffffu, lBs, 2);
        lA = lA * corrA + lAs;
        lB = lB * corrB + lBs;

#pragma unroll
        for (int nt = 0; nt < 16; nt++) {
            ob[nt][0] *= corrA; ob[nt][1] *= corrA;
            ob[nt][2] *= corrB; ob[nt][3] *= corrB;
        }

        // P fragments (pure register repack)
        uint32_t pa[4][4];
#pragma unroll
        for (int kt = 0; kt < 4; kt++) {
            pa[kt][0] = packh2(sc[2 * kt][0],     sc[2 * kt][1]);
            pa[kt][1] = packh2(sc[2 * kt][2],     sc[2 * kt][3]);
            pa[kt][2] = packh2(sc[2 * kt + 1][0], sc[2 * kt + 1][1]);
            pa[kt][3] = packh2(sc[2 * kt + 1][2], sc[2 * kt + 1][3]);
        }

        // O += P @ V
#pragma unroll
        for (int np = 0; np < 8; np++) {
#pragma unroll
            for (int kt = 0; kt < 4; kt++) {
                uint32_t row = kt * 16 + (((lane >> 3) & 1) << 3) + (lane & 7);
                uint32_t ch  = np * 2 + (lane >> 4);
                uint32_t v0, v1, v2, v3;
                LDSM_X4_T(v0, v1, v2, v3, Vbuf + swz256(row, ch));
                MMA16816(ob[2 * np],     pa[kt], v0, v1);
                MMA16816(ob[2 * np + 1], pa[kt], v2, v3);
            }
        }
        __syncthreads();
    }

    // normalize + store
    const float invA = 1.f / lA;
    const float invB = 1.f / lB;
    const size_t rowA = (qrowg + wq * 16 + g) * D_OUTC + h * HDIM;
#pragma unroll
    for (int nt = 0; nt < 16; nt++) {
        int col = nt * 8 + 2 * tig;
        *(uint32_t*)(ctxh + rowA + col) =
            packh2(ob[nt][0] * invA, ob[nt][1] * invA);
        *(uint32_t*)(ctxh + rowA + 8 * D_OUTC + col) =
            packh2(ob[nt][2] * invB, ob[nt][3] * invB);
    }
}

// ---------------------------------------------------------------------------
// Conversions
// ---------------------------------------------------------------------------
__global__ void conv_f2h_kernel(const float* __restrict__ in,
                                __half* __restrict__ out, int n)
{
    int i = (blockIdx.x * 256 + threadIdx.x) * 4;
    if (i < n) {
        float4 v = *reinterpret_cast<const float4*>(in + i);
        __half2* o = reinterpret_cast<__half2*>(out + i);
        o[0] = __floats2half2_rn(v.x, v.y);
        o[1] = __floats2half2_rn(v.z, v.w);
    }
}

// out[c][r] (half) = in[r][c] (float); in is RxC
__global__ void transpose_cvt_kernel(const float* __restrict__ in,
                                     __half* __restrict__ out, int R, int C)
{
    __shared__ float t[32][33];
    int bx = blockIdx.x * 32, by = blockIdx.y * 32;
#pragma unroll
    for (int i = 0; i < 32; i += 8)
        t[threadIdx.y + i][threadIdx.x] =
            in[(size_t)(by + threadIdx.y + i) * C + bx + threadIdx.x];
    __syncthreads();
#pragma unroll
    for (int i = 0; i < 32; i += 8)
        out[(size_t)(bx + threadIdx.y + i) * R + by + threadIdx.x] =
            __float2half_rn(t[threadIdx.x][threadIdx.y + i]);
}

// ---------------------------------------------------------------------------
// Launch
// ---------------------------------------------------------------------------
extern "C" void kernel_launch(void* const* d_in, const int* in_sizes, int n_in,
                              void* d_out, int out_size)
{
    const float* x    = (const float*)d_in[0];
    const float* Wq   = (const float*)d_in[1];
    const float* Wdkv = (const float*)d_in[2];
    const float* Wukv = (const float*)d_in[3];
    const float* Wout = (const float*)d_in[4];
    const float* bout = (const float*)d_in[5];
    float* out = (float*)d_out;

    __half *xh, *qh, *lath, *kvh, *ctxh, *wqT, *wdkvT, *wukvT, *woutT;
    cudaGetSymbolAddress((void**)&xh,    g_xh);
    cudaGetSymbolAddress((void**)&qh,    g_qh);
    cudaGetSymbolAddress((void**)&lath,  g_lath);
    cudaGetSymbolAddress((void**)&kvh,   g_kvh);
    cudaGetSymbolAddress((void**)&ctxh,  g_ctxh);
    cudaGetSymbolAddress((void**)&wqT,   g_wqT);
    cudaGetSymbolAddress((void**)&wdkvT, g_wdkvT);
    cudaGetSymbolAddress((void**)&wukvT, g_wukvT);
    cudaGetSymbolAddress((void**)&woutT, g_woutT);

    cudaFuncSetAttribute(gemm_h_kernel,
                         cudaFuncAttributeMaxDynamicSharedMemorySize, GEMM_SMEM);
    cudaFuncSetAttribute(attn_h_kernel,
                         cudaFuncAttributeMaxDynamicSharedMemorySize, ATTN_SMEM);

    dim3 tb(32, 8);

    // x -> fp16
    conv_f2h_kernel<<<(MTOT * D_INC) / 1024, 256>>>(x, xh, MTOT * D_INC);

    // weights -> fp16 transposed [N][K]
    transpose_cvt_kernel<<<dim3(D_OUTC / 32, D_INC / 32), tb>>>(Wq, wqT, D_INC, D_OUTC);
    transpose_cvt_kernel<<<dim3(LATENT / 32, D_INC / 32), tb>>>(Wdkv, wdkvT, D_INC, LATENT);
    transpose_cvt_kernel<<<dim3((2 * D_OUTC) / 32, LATENT / 32), tb>>>(Wukv, wukvT, LATENT, 2 * D_OUTC);
    transpose_cvt_kernel<<<dim3(D_INC / 32, D_OUTC / 32), tb>>>(Wout, woutT, D_OUTC, D_INC);

    // 1) q = x @ Wq  (fp16 out)
    gemm_h_kernel<<<dim3(D_OUTC / 128, MTOT / 128), 256, GEMM_SMEM>>>(
        xh, wqT, nullptr, qh, MTOT, D_OUTC, D_INC, D_INC, D_INC, D_OUTC, 1);

    // 2) latent = x @ Wdkv (fp16 out)
    gemm_h_kernel<<<dim3(LATENT / 128, MTOT / 128), 256, GEMM_SMEM>>>(
        xh, wdkvT, nullptr, lath, MTOT, LATENT, D_INC, D_INC, D_INC, LATENT, 1);

    // 3) kv = latent @ Wukv (fp16 out)
    gemm_h_kernel<<<dim3((2 * D_OUTC) / 128, MTOT / 128), 256, GEMM_SMEM>>>(
        lath, wukvT, nullptr, kvh, MTOT, 2 * D_OUTC, LATENT, LATENT, LATENT, 2 * D_OUTC, 1);

    // 4) attention -> ctx (fp16)
    attn_h_kernel<<<dim3(SEQ / 128, NHEADS, BATCH), 256, ATTN_SMEM>>>(qh, kvh, ctxh);

    // 5) out = ctx @ Wout + b (fp32 out)
    gemm_h_kernel<<<dim3(D_INC / 128, MTOT / 128), 256, GEMM_SMEM>>>(
        ctxh, woutT, bout, out, MTOT, D_INC, D_OUTC, D_OUTC, D_OUTC, D_INC, 0);
}

// round 4
// speedup vs baseline: 7.6645x; 1.0341x over previous
#include <cuda_runtime.h>
#include <cuda_fp16.h>
#include <cstdint>
#include <math.h>

// Problem constants
#define D_INC   2048
#define D_OUTC  2048
#define NHEADS  16
#define HDIM    128
#define LATENT  256
#define BATCH   2
#define SEQ     2048
#define MTOT    (BATCH * SEQ)        // 4096

#define NEG_BIG (-1.0e30f)

// ---------------------------------------------------------------------------
// Scratch (device globals; no allocation allowed)
// ---------------------------------------------------------------------------
__device__ __align__(16) __half g_xh  [(size_t)MTOT * D_INC];
__device__ __align__(16) __half g_qh  [(size_t)MTOT * D_OUTC];
__device__ __align__(16) __half g_lath[(size_t)MTOT * LATENT];
__device__ __align__(16) __half g_kvh [(size_t)MTOT * 2 * D_OUTC];
__device__ __align__(16) __half g_ctxh[(size_t)MTOT * D_OUTC];
__device__ __align__(16) __half g_wqdT [(size_t)(D_OUTC + LATENT) * D_INC]; // [2304][2048]
__device__ __align__(16) __half g_wukvT[(size_t)(2 * D_OUTC) * LATENT];
__device__ __align__(16) __half g_woutT[(size_t)D_INC * D_OUTC];

// ---------------------------------------------------------------------------
// PTX helpers
// ---------------------------------------------------------------------------
__device__ __forceinline__ uint32_t smem_u32(const void* p) {
    uint32_t a;
    asm("{ .reg .u64 t; cvta.to.shared.u64 t, %1; cvt.u32.u64 %0, t; }"
        : "=r"(a) : "l"(p));
    return a;
}

#define CP_ASYNC16(dst, src) \
    asm volatile("cp.async.cg.shared.global [%0], [%1], 16;" \
                 :: "r"(dst), "l"(src) : "memory")
#define CP_COMMIT() asm volatile("cp.async.commit_group;" ::: "memory")
#define CP_WAIT2()  asm volatile("cp.async.wait_group 2;" ::: "memory")
#define CP_WAIT1()  asm volatile("cp.async.wait_group 1;" ::: "memory")

#define LDSM_X4(r0, r1, r2, r3, a) \
    asm volatile("ldmatrix.sync.aligned.m8n8.x4.shared.b16 {%0,%1,%2,%3}, [%4];" \
                 : "=r"(r0), "=r"(r1), "=r"(r2), "=r"(r3) : "r"(a))
#define LDSM_X4_T(r0, r1, r2, r3, a) \
    asm volatile("ldmatrix.sync.aligned.m8n8.x4.trans.shared.b16 {%0,%1,%2,%3}, [%4];" \
                 : "=r"(r0), "=r"(r1), "=r"(r2), "=r"(r3) : "r"(a))

#define MMA16816(d, a, b0_, b1_) \
    asm volatile("mma.sync.aligned.m16n8k16.row.col.f32.f16.f16.f32 " \
                 "{%0,%1,%2,%3}, {%4,%5,%6,%7}, {%8,%9}, {%0,%1,%2,%3};" \
                 : "+f"((d)[0]), "+f"((d)[1]), "+f"((d)[2]), "+f"((d)[3]) \
                 : "r"((a)[0]), "r"((a)[1]), "r"((a)[2]), "r"((a)[3]), \
                   "r"(b0_), "r"(b1_))

__device__ __forceinline__ uint32_t swz128(uint32_t r, uint32_t c) {
    return r * 128u + ((c ^ (r & 7u)) << 4);
}
__device__ __forceinline__ uint32_t swz256(uint32_t r, uint32_t c) {
    return r * 256u + ((c ^ (r & 7u)) << 4);
}
__device__ __forceinline__ uint32_t packh2(float a, float b) {
    __half2 h = __floats2half2_rn(a, b);
    return *reinterpret_cast<uint32_t*>(&h);
}

// ---------------------------------------------------------------------------
// fp16 GEMM: C[M,N] = A[M,K] @ Bt[N,K]^T
// CTA 128(M) x 256(N), BK=64, 8 warps (2M x 4N), warp tile 64x64.
// 4-stage cp.async pipeline, one __syncthreads per stage.
// Stage smem: A 16KB + B 32KB = 48KB; 4 stages = 192KB.
// Epilogue routes col<nsplit -> C (ldc), else -> C2 (ldc2). fp32out => bias add.
// ---------------------------------------------------------------------------
#define GSTAGE     49152
#define GEMM_SMEM  (4 * GSTAGE + 1024)

__device__ __forceinline__ void gemm_load_stage(
    uint32_t buf, const __half* __restrict__ A, const __half* __restrict__ Bt,
    int lda, int ldb, int m0, int n0, int k0, int tid)
{
    const uint32_t bufA = buf, bufB = buf + 16384;
#pragma unroll
    for (int i = 0; i < 4; i++) {            // A: 128 rows x 8 chunks
        int f = tid + i * 256;
        int r = f >> 3, c = f & 7;
        CP_ASYNC16(bufA + swz128(r, c),
                   A + (size_t)(m0 + r) * lda + k0 + c * 8);
    }
#pragma unroll
    for (int i = 0; i < 8; i++) {            // B: 256 rows x 8 chunks
        int f = tid + i * 256;
        int r = f >> 3, c = f & 7;
        CP_ASYNC16(bufB + swz128(r, c),
                   Bt + (size_t)(n0 + r) * ldb + k0 + c * 8);
    }
}

__global__ __launch_bounds__(256, 1)
void gemm_h_kernel(const __half* __restrict__ A, const __half* __restrict__ Bt,
                   const float* __restrict__ bias,
                   void* __restrict__ Cv, int ldc,
                   void* __restrict__ C2v, int ldc2, int nsplit,
                   int K, int lda, int ldb, int fp32out)
{
    extern __shared__ char smem_raw[];
    uint32_t sb = (smem_u32(smem_raw) + 1023u) & ~1023u;

    const int tid  = threadIdx.x;
    const int wid  = tid >> 5;
    const int lane = tid & 31;
    const int wm   = wid & 1;        // 2 M halves of 64
    const int wn   = wid >> 1;       // 4 N quarters of 64
    const int g    = lane >> 2;
    const int tig  = lane & 3;
    const int m0 = blockIdx.y * 128;
    const int n0 = blockIdx.x * 256;

    float acc[4][8][4];
#pragma unroll
    for (int mt = 0; mt < 4; mt++)
#pragma unroll
        for (int nt = 0; nt < 8; nt++)
#pragma unroll
            for (int e = 0; e < 4; e++) acc[mt][nt][e] = 0.f;

    const int S = K >> 6;            // all shapes have S >= 4

    gemm_load_stage(sb,              A, Bt, lda, ldb, m0, n0, 0,   tid); CP_COMMIT();
    gemm_load_stage(sb + GSTAGE,     A, Bt, lda, ldb, m0, n0, 64,  tid); CP_COMMIT();
    gemm_load_stage(sb + 2 * GSTAGE, A, Bt, lda, ldb, m0, n0, 128, tid); CP_COMMIT();

    for (int s = 0; s < S; s++) {
        CP_WAIT2();                  // stage s resident
        __syncthreads();             // all warps done with stage s-1 reads
        if (s + 3 < S)
            gemm_load_stage(sb + ((s + 3) & 3) * GSTAGE,
                            A, Bt, lda, ldb, m0, n0, (s + 3) * 64, tid);
        CP_COMMIT();

        const uint32_t bA = sb + (s & 3) * GSTAGE;
        const uint32_t bB = bA + 16384;

#pragma unroll
        for (int kt = 0; kt < 4; kt++) {
            uint32_t af[4][4];
#pragma unroll
            for (int mt = 0; mt < 4; mt++) {
                uint32_t row = wm * 64 + mt * 16 + (lane & 15);
                uint32_t ch  = kt * 2 + (lane >> 4);
                LDSM_X4(af[mt][0], af[mt][1], af[mt][2], af[mt][3],
                        bA + swz128(row, ch));
            }
            uint32_t bf[8][2];
#pragma unroll
            for (int np = 0; np < 4; np++) {
                uint32_t row = wn * 64 + np * 16 + ((lane >> 4) << 3) + (lane & 7);
                uint32_t ch  = kt * 2 + ((lane >> 3) & 1);
                uint32_t r0, r1, r2, r3;
                LDSM_X4(r0, r1, r2, r3, bB + swz128(row, ch));
                bf[2 * np][0] = r0; bf[2 * np][1] = r1;
                bf[2 * np + 1][0] = r2; bf[2 * np + 1][1] = r3;
            }
#pragma unroll
            for (int mt = 0; mt < 4; mt++)
#pragma unroll
                for (int nt = 0; nt < 8; nt++)
                    MMA16816(acc[mt][nt], af[mt], bf[nt][0], bf[nt][1]);
        }
    }

    // Epilogue
#pragma unroll
    for (int mt = 0; mt < 4; mt++) {
#pragma unroll
        for (int nt = 0; nt < 8; nt++) {
            int row = m0 + wm * 64 + mt * 16 + g;
            int col = n0 + wn * 64 + nt * 8 + 2 * tig;
            float* a = acc[mt][nt];
            if (fp32out) {
                float* C = (float*)Cv;
                float b0 = bias ? bias[col]     : 0.f;
                float b1 = bias ? bias[col + 1] : 0.f;
                *(float2*)(C + (size_t)row * ldc + col) =
                    make_float2(a[0] + b0, a[1] + b1);
                *(float2*)(C + (size_t)(row + 8) * ldc + col) =
                    make_float2(a[2] + b0, a[3] + b1);
            } else if (col < nsplit) {
                __half* C = (__half*)Cv;
                *(uint32_t*)(C + (size_t)row * ldc + col)       = packh2(a[0], a[1]);
                *(uint32_t*)(C + (size_t)(row + 8) * ldc + col) = packh2(a[2], a[3]);
            } else {
                __half* C = (__half*)C2v;
                int c2 = col - nsplit;
                *(uint32_t*)(C + (size_t)row * ldc2 + c2)       = packh2(a[0], a[1]);
                *(uint32_t*)(C + (size_t)(row + 8) * ldc2 + c2) = packh2(a[2], a[3]);
            }
        }
    }
}

// ---------------------------------------------------------------------------
// Flash attention, fp16 mma.sync, causal. BQ=128, BK=128, 8 warps x 16 rows.
// smem: Q 32KB + 2 stages x (K 32KB + V 32KB) = 160KB.
// ---------------------------------------------------------------------------
#define ATTN_SMEM (163840 + 1024)

__global__ __launch_bounds__(256, 1)
void attn_h_kernel(const __half* __restrict__ qh, const __half* __restrict__ kvh,
                   __half* __restrict__ ctxh)
{
    extern __shared__ char smem_raw[];
    uint32_t sb = (smem_u32(smem_raw) + 1023u) & ~1023u;
    const uint32_t Qs  = sb;
    const uint32_t KB0 = sb + 32768;           // K stage0
    const uint32_t VB0 = sb + 65536;           // V stage0
    const uint32_t KB1 = sb + 98304;
    const uint32_t VB1 = sb + 131072;

    const int tid  = threadIdx.x;
    const int wq   = tid >> 5;
    const int lane = tid & 31;
    const int g    = lane >> 2;
    const int tig  = lane & 3;
    const int qb = gridDim.x - 1 - blockIdx.x;   // heavy tiles first
    const int h  = blockIdx.y;
    const int b  = blockIdx.z;

    const int qrow0 = qb * 128;
    const size_t qrowg  = (size_t)b * SEQ + qrow0;
    const size_t kvrowg = (size_t)b * SEQ;
    const float SCALE = 0.08838834764831845f;

    // Prologue: Q + stage0 K/V (group 0)
#pragma unroll
    for (int i = 0; i < 8; i++) {
        int f = tid + i * 256;
        int r = f >> 4, c = f & 15;
        CP_ASYNC16(Qs + swz256(r, c),
                   qh + (qrowg + r) * D_OUTC + h * HDIM + c * 8);
        const __half* src = kvh + (kvrowg + r) * (2 * D_OUTC) + h * HDIM + c * 8;
        CP_ASYNC16(KB0 + swz256(r, c), src);
        CP_ASYNC16(VB0 + swz256(r, c), src + D_OUTC);
    }
    CP_COMMIT();

    float ob[16][4];
#pragma unroll
    for (int nt = 0; nt < 16; nt++)
#pragma unroll
        for (int e = 0; e < 4; e++) ob[nt][e] = 0.f;
    float mA = NEG_BIG, mB = NEG_BIG, lA = 0.f, lB = 0.f;
    uint32_t qf[8][4];
    const int grA = qrow0 + wq * 16 + g;
    const int grB = grA + 8;

    for (int kb = 0; kb <= qb; kb++) {
        __syncthreads();             // everyone done reading buffer (kb-1)&1
        if (kb + 1 <= qb) {
            const uint32_t nK = ((kb + 1) & 1) ? KB1 : KB0;
            const uint32_t nV = ((kb + 1) & 1) ? VB1 : VB0;
#pragma unroll
            for (int i = 0; i < 8; i++) {
                int f = tid + i * 256;
                int r = f >> 4, c = f & 15;
                const __half* src = kvh + (kvrowg + (size_t)(kb + 1) * 128 + r) * (2 * D_OUTC)
                                    + h * HDIM + c * 8;
                CP_ASYNC16(nK + swz256(r, c), src);
                CP_ASYNC16(nV + swz256(r, c), src + D_OUTC);
            }
        }
        CP_COMMIT();
        CP_WAIT1();                  // stage kb resident
        __syncthreads();

        if (kb == 0) {
#pragma unroll
            for (int kt = 0; kt < 8; kt++) {
                uint32_t row = wq * 16 + (lane & 15);
                uint32_t ch  = kt * 2 + (lane >> 4);
                LDSM_X4(qf[kt][0], qf[kt][1], qf[kt][2], qf[kt][3],
                        Qs + swz256(row, ch));
            }
        }

        const uint32_t Kbuf = (kb & 1) ? KB1 : KB0;
        const uint32_t Vbuf = (kb & 1) ? VB1 : VB0;

        // S = Q @ K^T  (16 q-rows x 128 keys per warp)
        float sc[16][4];
#pragma unroll
        for (int nt = 0; nt < 16; nt++)
#pragma unroll
            for (int e = 0; e < 4; e++) sc[nt][e] = 0.f;

#pragma unroll
        for (int np = 0; np < 8; np++) {
#pragma unroll
            for (int kt = 0; kt < 8; kt++) {
                uint32_t row = np * 16 + ((lane >> 4) << 3) + (lane & 7);
                uint32_t ch  = kt * 2 + ((lane >> 3) & 1);
                uint32_t r0, r1, r2, r3;
                LDSM_X4(r0, r1, r2, r3, Kbuf + swz256(row, ch));
                MMA16816(sc[2 * np],     qf[kt], r0, r1);
                MMA16816(sc[2 * np + 1], qf[kt], r2, r3);
            }
        }

        // scale + causal mask (only diagonal block needs it)
        const bool diag = (kb == qb);
#pragma unroll
        for (int nt = 0; nt < 16; nt++) {
            int c0 = kb * 128 + nt * 8 + 2 * tig;
            sc[nt][0] *= SCALE; sc[nt][1] *= SCALE;
            sc[nt][2] *= SCALE; sc[nt][3] *= SCALE;
            if (diag) {
                if (c0     > grA) sc[nt][0] = NEG_BIG;
                if (c0 + 1 > grA) sc[nt][1] = NEG_BIG;
                if (c0     > grB) sc[nt][2] = NEG_BIG;
                if (c0 + 1 > grB) sc[nt][3] = NEG_BIG;
            }
        }

        // online softmax (rows g, g+8); quad reduce over tig
        float mAn = NEG_BIG, mBn = NEG_BIG;
#pragma unroll
        for (int nt = 0; nt < 16; nt++) {
            mAn = fmaxf(mAn, fmaxf(sc[nt][0], sc[nt][1]));
            mBn = fmaxf(mBn, fmaxf(sc[nt][2], sc[nt][3]));
        }
        mAn = fmaxf(mAn, __shfl_xor_sync(0xffffffffu, mAn, 1));
        mAn = fmaxf(mAn, __shfl_xor_sync(0xffffffffu, mAn, 2));
        mBn = fmaxf(mBn, __shfl_xor_sync(0xffffffffu, mBn, 1));
        mBn = fmaxf(mBn, __shfl_xor_sync(0xffffffffu, mBn, 2));
        float mAnew = fmaxf(mA, mAn);
        float mBnew = fmaxf(mB, mBn);
        float corrA = __expf(mA - mAnew);
        float corrB = __expf(mB - mBnew);
        mA = mAnew; mB = mBnew;

        float lAs = 0.f, lBs = 0.f;
#pragma unroll
        for (int nt = 0; nt < 16; nt++) {
            sc[nt][0] = __expf(sc[nt][0] - mA);
            sc[nt][1] = __expf(sc[nt][1] - mA);
            sc[nt][2] = __expf(sc[nt][2] - mB);
            sc[nt][3] = __expf(sc[nt][3] - mB);
            lAs += sc[nt][0] + sc[nt][1];
            lBs += sc[nt][2] + sc[nt][3];
        }
        lAs += __shfl_xor_sync(0xffffffffu, lAs, 1);
        lAs += __shfl_xor_sync(0xffffffffu, lAs, 2);
        lBs += __shfl_xor_sync(0xffffffffu, lBs, 1);
        lBs += __shfl_xor_sync(0xffffffffu, lBs, 2);
        lA = lA * corrA + lAs;
        lB = lB * corrB + lBs;

#pragma unroll
        for (int nt = 0; nt < 16; nt++) {
            ob[nt][0] *= corrA; ob[nt][1] *= corrA;
            ob[nt][2] *= corrB; ob[nt][3] *= corrB;
        }

        // P fragments (register repack)
        uint32_t pa[8][4];
#pragma unroll
        for (int kt = 0; kt < 8; kt++) {
            pa[kt][0] = packh2(sc[2 * kt][0],     sc[2 * kt][1]);
            pa[kt][1] = packh2(sc[2 * kt][2],     sc[2 * kt][3]);
            pa[kt][2] = packh2(sc[2 * kt + 1][0], sc[2 * kt + 1][1]);
            pa[kt][3] = packh2(sc[2 * kt + 1][2], sc[2 * kt + 1][3]);
        }

        // O += P @ V
#pragma unroll
        for (int np = 0; np < 8; np++) {
#pragma unroll
            for (int kt = 0; kt < 8; kt++) {
                uint32_t row = kt * 16 + (((lane >> 3) & 1) << 3) + (lane & 7);
                uint32_t ch  = np * 2 + (lane >> 4);
                uint32_t v0, v1, v2, v3;
                LDSM_X4_T(v0, v1, v2, v3, Vbuf + swz256(row, ch));
                MMA16816(ob[2 * np],     pa[kt], v0, v1);
                MMA16816(ob[2 * np + 1], pa[kt], v2, v3);
            }
        }
    }

    // normalize + store
    const float invA = 1.f / lA;
    const float invB = 1.f / lB;
    const size_t rowA = (qrowg + wq * 16 + g) * D_OUTC + h * HDIM;
#pragma unroll
    for (int nt = 0; nt < 16; nt++) {
        int col = nt * 8 + 2 * tig;
        *(uint32_t*)(ctxh + rowA + col) =
            packh2(ob[nt][0] * invA, ob[nt][1] * invA);
        *(uint32_t*)(ctxh + rowA + 8 * D_OUTC + col) =
            packh2(ob[nt][2] * invB, ob[nt][3] * invB);
    }
}

// ---------------------------------------------------------------------------
// Conversions
// ---------------------------------------------------------------------------
__global__ void conv_f2h_kernel(const float* __restrict__ in,
                                __half* __restrict__ out, int n)
{
    int i = (blockIdx.x * 256 + threadIdx.x) * 4;
    if (i < n) {
        float4 v = *reinterpret_cast<const float4*>(in + i);
        __half2* o = reinterpret_cast<__half2*>(out + i);
        o[0] = __floats2half2_rn(v.x, v.y);
        o[1] = __floats2half2_rn(v.z, v.w);
    }
}

// out[c][r] (half, ld=R) = in[r][c] (float, RxC)
__global__ void transpose_cvt_kernel(const float* __restrict__ in,
                                     __half* __restrict__ out, int R, int C)
{
    __shared__ float t[32][33];
    int bx = blockIdx.x * 32, by = blockIdx.y * 32;
#pragma unroll
    for (int i = 0; i < 32; i += 8)
        t[threadIdx.y + i][threadIdx.x] =
            in[(size_t)(by + threadIdx.y + i) * C + bx + threadIdx.x];
    __syncthreads();
#pragma unroll
    for (int i = 0; i < 32; i += 8)
        out[(size_t)(bx + threadIdx.y + i) * R + by + threadIdx.x] =
            __float2half_rn(t[threadIdx.x][threadIdx.y + i]);
}

// ---------------------------------------------------------------------------
// Launch
// ---------------------------------------------------------------------------
extern "C" void kernel_launch(void* const* d_in, const int* in_sizes, int n_in,
                              void* d_out, int out_size)
{
    const float* x    = (const float*)d_in[0];
    const float* Wq   = (const float*)d_in[1];
    const float* Wdkv = (const float*)d_in[2];
    const float* Wukv = (const float*)d_in[3];
    const float* Wout = (const float*)d_in[4];
    const float* bout = (const float*)d_in[5];
    float* out = (float*)d_out;

    __half *xh, *qh, *lath, *kvh, *ctxh, *wqdT, *wukvT, *woutT;
    cudaGetSymbolAddress((void**)&xh,    g_xh);
    cudaGetSymbolAddress((void**)&qh,    g_qh);
    cudaGetSymbolAddress((void**)&lath,  g_lath);
    cudaGetSymbolAddress((void**)&kvh,   g_kvh);
    cudaGetSymbolAddress((void**)&ctxh,  g_ctxh);
    cudaGetSymbolAddress((void**)&wqdT,  g_wqdT);
    cudaGetSymbolAddress((void**)&wukvT, g_wukvT);
    cudaGetSymbolAddress((void**)&woutT, g_woutT);

    cudaFuncSetAttribute(gemm_h_kernel,
                         cudaFuncAttributeMaxDynamicSharedMemorySize, GEMM_SMEM);
    cudaFuncSetAttribute(attn_h_kernel,
                         cudaFuncAttributeMaxDynamicSharedMemorySize, ATTN_SMEM);

    dim3 tb(32, 8);

    // x -> fp16
    conv_f2h_kernel<<<(MTOT * D_INC) / 1024, 256>>>(x, xh, MTOT * D_INC);

    // weights -> fp16 transposed [N][K]; Wq and Wdkv stacked into one buffer
    transpose_cvt_kernel<<<dim3(D_OUTC / 32, D_INC / 32), tb>>>(Wq, wqdT, D_INC, D_OUTC);
    transpose_cvt_kernel<<<dim3(LATENT / 32, D_INC / 32), tb>>>(
        Wdkv, wqdT + (size_t)D_OUTC * D_INC, D_INC, LATENT);
    transpose_cvt_kernel<<<dim3((2 * D_OUTC) / 32, LATENT / 32), tb>>>(Wukv, wukvT, LATENT, 2 * D_OUTC);
    transpose_cvt_kernel<<<dim3(D_INC / 32, D_OUTC / 32), tb>>>(Wout, woutT, D_OUTC, D_INC);

    // 1) [q | latent] = x @ [Wq | Wdkv]   (N = 2304, split at 2048)
    gemm_h_kernel<<<dim3((D_OUTC + LATENT) / 256, MTOT / 128), 256, GEMM_SMEM>>>(
        xh, wqdT, nullptr, qh, D_OUTC, lath, LATENT, D_OUTC,
        D_INC, D_INC, D_INC, 0);

    // 2) kv = latent @ Wukv               (N = 4096)
    gemm_h_kernel<<<dim3((2 * D_OUTC) / 256, MTOT / 128), 256, GEMM_SMEM>>>(
        lath, wukvT, nullptr, kvh, 2 * D_OUTC, nullptr, 0, 1 << 30,
        LATENT, LATENT, LATENT, 0);

    // 3) attention -> ctx
    attn_h_kernel<<<dim3(SEQ / 128, NHEADS, BATCH), 256, ATTN_SMEM>>>(qh, kvh, ctxh);

    // 4) out = ctx @ Wout + b  (fp32)
    gemm_h_kernel<<<dim3(D_INC / 256, MTOT / 128), 256, GEMM_SMEM>>>(
        ctxh, woutT, bout, out, D_INC, nullptr, 0, 1 << 30,
        D_OUTC, D_OUTC, D_OUTC, 1);
}

// round 5
// speedup vs baseline: 7.9412x; 1.0361x over previous
#include <cuda_runtime.h>
#include <cuda_fp16.h>
#include <cstdint>
#include <math.h>

// Problem constants
#define D_INC   2048
#define D_OUTC  2048
#define NHEADS  16
#define HDIM    128
#define LATENT  256
#define BATCH   2
#define SEQ     2048
#define MTOT    (BATCH * SEQ)        // 4096

#define NEG_BIG (-1.0e30f)
// rsqrt(128) * log2(e)  — folded into q projection; softmax uses ex2
#define QK_SCALE 0.12751875732f

// ---------------------------------------------------------------------------
// Scratch (device globals; no allocation allowed)
// ---------------------------------------------------------------------------
__device__ __align__(16) __half g_xh  [(size_t)MTOT * D_INC];
__device__ __align__(16) __half g_qh  [(size_t)MTOT * D_OUTC];
__device__ __align__(16) __half g_lath[(size_t)MTOT * LATENT];
__device__ __align__(16) __half g_kvh [(size_t)MTOT * 2 * D_OUTC];
__device__ __align__(16) __half g_ctxh[(size_t)MTOT * D_OUTC];
__device__ __align__(16) __half g_wqdT [(size_t)(D_OUTC + LATENT) * D_INC];
__device__ __align__(16) __half g_wukvT[(size_t)(2 * D_OUTC) * LATENT];
__device__ __align__(16) __half g_woutT[(size_t)D_INC * D_OUTC];

// ---------------------------------------------------------------------------
// PTX helpers
// ---------------------------------------------------------------------------
__device__ __forceinline__ uint32_t smem_u32(const void* p) {
    uint32_t a;
    asm("{ .reg .u64 t; cvta.to.shared.u64 t, %1; cvt.u32.u64 %0, t; }"
        : "=r"(a) : "l"(p));
    return a;
}
__device__ __forceinline__ float ex2f(float x) {
    float y;
    asm("ex2.approx.f32 %0, %1;" : "=f"(y) : "f"(x));
    return y;
}

#define CP_ASYNC16(dst, src) \
    asm volatile("cp.async.cg.shared.global [%0], [%1], 16;" \
                 :: "r"(dst), "l"(src) : "memory")
#define CP_COMMIT() asm volatile("cp.async.commit_group;" ::: "memory")
#define CP_WAIT2()  asm volatile("cp.async.wait_group 2;" ::: "memory")
#define CP_WAIT1()  asm volatile("cp.async.wait_group 1;" ::: "memory")

#define LDSM_X4(r0, r1, r2, r3, a) \
    asm volatile("ldmatrix.sync.aligned.m8n8.x4.shared.b16 {%0,%1,%2,%3}, [%4];" \
                 : "=r"(r0), "=r"(r1), "=r"(r2), "=r"(r3) : "r"(a))
#define LDSM_X4_T(r0, r1, r2, r3, a) \
    asm volatile("ldmatrix.sync.aligned.m8n8.x4.trans.shared.b16 {%0,%1,%2,%3}, [%4];" \
                 : "=r"(r0), "=r"(r1), "=r"(r2), "=r"(r3) : "r"(a))

#define MMA16816(d, a, b0_, b1_) \
    asm volatile("mma.sync.aligned.m16n8k16.row.col.f32.f16.f16.f32 " \
                 "{%0,%1,%2,%3}, {%4,%5,%6,%7}, {%8,%9}, {%0,%1,%2,%3};" \
                 : "+f"((d)[0]), "+f"((d)[1]), "+f"((d)[2]), "+f"((d)[3]) \
                 : "r"((a)[0]), "r"((a)[1]), "r"((a)[2]), "r"((a)[3]), \
                   "r"(b0_), "r"(b1_))

__device__ __forceinline__ uint32_t swz128(uint32_t r, uint32_t c) {
    return r * 128u + ((c ^ (r & 7u)) << 4);
}
__device__ __forceinline__ uint32_t swz256(uint32_t r, uint32_t c) {
    return r * 256u + ((c ^ (r & 7u)) << 4);
}
__device__ __forceinline__ uint32_t packh2(float a, float b) {
    __half2 h = __floats2half2_rn(a, b);
    return *reinterpret_cast<uint32_t*>(&h);
}

// ---------------------------------------------------------------------------
// fp16 GEMM: C[M,N] = A[M,K] @ Bt[N,K]^T
// CTA 128(M) x 256(N), BK=64, 8 warps (2M x 4N), warp tile 64x64.
// 4-stage cp.async pipeline + double-buffered ldmatrix fragments.
// ---------------------------------------------------------------------------
#define GSTAGE     49152
#define GEMM_SMEM  (4 * GSTAGE + 1024)

__device__ __forceinline__ void gemm_load_stage(
    uint32_t buf, const __half* __restrict__ A, const __half* __restrict__ Bt,
    int lda, int ldb, int m0, int n0, int k0, int tid)
{
    const uint32_t bufA = buf, bufB = buf + 16384;
#pragma unroll
    for (int i = 0; i < 4; i++) {
        int f = tid + i * 256;
        int r = f >> 3, c = f & 7;
        CP_ASYNC16(bufA + swz128(r, c),
                   A + (size_t)(m0 + r) * lda + k0 + c * 8);
    }
#pragma unroll
    for (int i = 0; i < 8; i++) {
        int f = tid + i * 256;
        int r = f >> 3, c = f & 7;
        CP_ASYNC16(bufB + swz128(r, c),
                   Bt + (size_t)(n0 + r) * ldb + k0 + c * 8);
    }
}

__global__ __launch_bounds__(256, 1)
void gemm_h_kernel(const __half* __restrict__ A, const __half* __restrict__ Bt,
                   const float* __restrict__ bias,
                   void* __restrict__ Cv, int ldc,
                   void* __restrict__ C2v, int ldc2, int nsplit,
                   int K, int lda, int ldb, int fp32out, float cscale)
{
    extern __shared__ char smem_raw[];
    uint32_t sb = (smem_u32(smem_raw) + 1023u) & ~1023u;

    const int tid  = threadIdx.x;
    const int wid  = tid >> 5;
    const int lane = tid & 31;
    const int wm   = wid & 1;
    const int wn   = wid >> 1;
    const int g    = lane >> 2;
    const int tig  = lane & 3;
    const int m0 = blockIdx.y * 128;
    const int n0 = blockIdx.x * 256;

    float acc[4][8][4];
#pragma unroll
    for (int mt = 0; mt < 4; mt++)
#pragma unroll
        for (int nt = 0; nt < 8; nt++)
#pragma unroll
            for (int e = 0; e < 4; e++) acc[mt][nt][e] = 0.f;

    // fragment addressing (constant per thread, varies by kt)
    const uint32_t a_row = wm * 64 + (lane & 15);
    const uint32_t a_chb = lane >> 4;
    const uint32_t b_row = wn * 64 + ((lane >> 4) << 3) + (lane & 7);
    const uint32_t b_chb = (lane >> 3) & 1;

    const int S = K >> 6;

    gemm_load_stage(sb,              A, Bt, lda, ldb, m0, n0, 0,   tid); CP_COMMIT();
    gemm_load_stage(sb + GSTAGE,     A, Bt, lda, ldb, m0, n0, 64,  tid); CP_COMMIT();
    gemm_load_stage(sb + 2 * GSTAGE, A, Bt, lda, ldb, m0, n0, 128, tid); CP_COMMIT();

    uint32_t af[2][4][4], bf[2][8][2];

    for (int s = 0; s < S; s++) {
        CP_WAIT2();
        __syncthreads();
        if (s + 3 < S)
            gemm_load_stage(sb + ((s + 3) & 3) * GSTAGE,
                            A, Bt, lda, ldb, m0, n0, (s + 3) * 64, tid);
        CP_COMMIT();

        const uint32_t bA = sb + (s & 3) * GSTAGE;
        const uint32_t bB = bA + 16384;

        // prime kt=0 fragments
#pragma unroll
        for (int mt = 0; mt < 4; mt++)
            LDSM_X4(af[0][mt][0], af[0][mt][1], af[0][mt][2], af[0][mt][3],
                    bA + swz128(a_row + mt * 16, a_chb));
#pragma unroll
        for (int np = 0; np < 4; np++) {
            uint32_t r0, r1, r2, r3;
            LDSM_X4(r0, r1, r2, r3, bB + swz128(b_row + np * 16, b_chb));
            bf[0][2 * np][0] = r0; bf[0][2 * np][1] = r1;
            bf[0][2 * np + 1][0] = r2; bf[0][2 * np + 1][1] = r3;
        }

#pragma unroll
        for (int kt = 0; kt < 4; kt++) {
            const int cur = kt & 1, nxt = cur ^ 1;
            if (kt < 3) {
                const uint32_t ch = (kt + 1) * 2;
#pragma unroll
                for (int mt = 0; mt < 4; mt++)
                    LDSM_X4(af[nxt][mt][0], af[nxt][mt][1],
                            af[nxt][mt][2], af[nxt][mt][3],
                            bA + swz128(a_row + mt * 16, ch + a_chb));
#pragma unroll
                for (int np = 0; np < 4; np++) {
                    uint32_t r0, r1, r2, r3;
                    LDSM_X4(r0, r1, r2, r3,
                            bB + swz128(b_row + np * 16, ch + b_chb));
                    bf[nxt][2 * np][0] = r0; bf[nxt][2 * np][1] = r1;
                    bf[nxt][2 * np + 1][0] = r2; bf[nxt][2 * np + 1][1] = r3;
                }
            }
#pragma unroll
            for (int mt = 0; mt < 4; mt++)
#pragma unroll
                for (int nt = 0; nt < 8; nt++)
                    MMA16816(acc[mt][nt], af[cur][mt], bf[cur][nt][0], bf[cur][nt][1]);
        }
    }

    // Epilogue
#pragma unroll
    for (int mt = 0; mt < 4; mt++) {
#pragma unroll
        for (int nt = 0; nt < 8; nt++) {
            int row = m0 + wm * 64 + mt * 16 + g;
            int col = n0 + wn * 64 + nt * 8 + 2 * tig;
            float* a = acc[mt][nt];
            if (fp32out) {
                float* C = (float*)Cv;
                float b0 = bias ? bias[col]     : 0.f;
                float b1 = bias ? bias[col + 1] : 0.f;
                *(float2*)(C + (size_t)row * ldc + col) =
                    make_float2(a[0] + b0, a[1] + b1);
                *(float2*)(C + (size_t)(row + 8) * ldc + col) =
                    make_float2(a[2] + b0, a[3] + b1);
            } else if (col < nsplit) {
                __half* C = (__half*)Cv;
                *(uint32_t*)(C + (size_t)row * ldc + col) =
                    packh2(a[0] * cscale, a[1] * cscale);
                *(uint32_t*)(C + (size_t)(row + 8) * ldc + col) =
                    packh2(a[2] * cscale, a[3] * cscale);
            } else {
                __half* C = (__half*)C2v;
                int c2 = col - nsplit;
                *(uint32_t*)(C + (size_t)row * ldc2 + c2)       = packh2(a[0], a[1]);
                *(uint32_t*)(C + (size_t)(row + 8) * ldc2 + c2) = packh2(a[2], a[3]);
            }
        }
    }
}

// ---------------------------------------------------------------------------
// Flash attention, fp16 mma.sync, causal. BQ=128, BK=128, 8 warps x 16 rows.
// q is pre-scaled by rsqrt(128)*log2(e); softmax uses ex2.
// smem: Q 32KB + 2 stages x (K 32KB + V 32KB) = 160KB.
// ---------------------------------------------------------------------------
#define ATTN_SMEM (163840 + 1024)

__global__ __launch_bounds__(256, 1)
void attn_h_kernel(const __half* __restrict__ qh, const __half* __restrict__ kvh,
                   __half* __restrict__ ctxh)
{
    extern __shared__ char smem_raw[];
    uint32_t sb = (smem_u32(smem_raw) + 1023u) & ~1023u;
    const uint32_t Qs  = sb;
    const uint32_t KB0 = sb + 32768;
    const uint32_t VB0 = sb + 65536;
    const uint32_t KB1 = sb + 98304;
    const uint32_t VB1 = sb + 131072;

    const int tid  = threadIdx.x;
    const int wq   = tid >> 5;
    const int lane = tid & 31;
    const int g    = lane >> 2;
    const int tig  = lane & 3;
    const int qb = gridDim.x - 1 - blockIdx.x;
    const int h  = blockIdx.y;
    const int b  = blockIdx.z;

    const int qrow0 = qb * 128;
    const size_t qrowg  = (size_t)b * SEQ + qrow0;
    const size_t kvrowg = (size_t)b * SEQ;

    // Prologue: Q + stage0 K/V
#pragma unroll
    for (int i = 0; i < 8; i++) {
        int f = tid + i * 256;
        int r = f >> 4, c = f & 15;
        CP_ASYNC16(Qs + swz256(r, c),
                   qh + (qrowg + r) * D_OUTC + h * HDIM + c * 8);
        const __half* src = kvh + (kvrowg + r) * (2 * D_OUTC) + h * HDIM + c * 8;
        CP_ASYNC16(KB0 + swz256(r, c), src);
        CP_ASYNC16(VB0 + swz256(r, c), src + D_OUTC);
    }
    CP_COMMIT();

    float ob[16][4];
#pragma unroll
    for (int nt = 0; nt < 16; nt++)
#pragma unroll
        for (int e = 0; e < 4; e++) ob[nt][e] = 0.f;
    float mA = NEG_BIG, mB = NEG_BIG, lA = 0.f, lB = 0.f;
    uint32_t qf[8][4];
    const int grA = qrow0 + wq * 16 + g;
    const int grB = grA + 8;

    // per-thread fragment address components
    const uint32_t k_rowb = ((lane >> 4) << 3) + (lane & 7);
    const uint32_t k_chb  = (lane >> 3) & 1;
    const uint32_t v_rowb = (((lane >> 3) & 1) << 3) + (lane & 7);
    const uint32_t v_chb  = lane >> 4;

    for (int kb = 0; kb <= qb; kb++) {
        __syncthreads();
        if (kb + 1 <= qb) {
            const uint32_t nK = ((kb + 1) & 1) ? KB1 : KB0;
            const uint32_t nV = ((kb + 1) & 1) ? VB1 : VB0;
#pragma unroll
            for (int i = 0; i < 8; i++) {
                int f = tid + i * 256;
                int r = f >> 4, c = f & 15;
                const __half* src = kvh + (kvrowg + (size_t)(kb + 1) * 128 + r) * (2 * D_OUTC)
                                    + h * HDIM + c * 8;
                CP_ASYNC16(nK + swz256(r, c), src);
                CP_ASYNC16(nV + swz256(r, c), src + D_OUTC);
            }
        }
        CP_COMMIT();
        CP_WAIT1();
        __syncthreads();

        if (kb == 0) {
#pragma unroll
            for (int kt = 0; kt < 8; kt++) {
                uint32_t row = wq * 16 + (lane & 15);
                uint32_t ch  = kt * 2 + (lane >> 4);
                LDSM_X4(qf[kt][0], qf[kt][1], qf[kt][2], qf[kt][3],
                        Qs + swz256(row, ch));
            }
        }

        const uint32_t Kbuf = (kb & 1) ? KB1 : KB0;
        const uint32_t Vbuf = (kb & 1) ? VB1 : VB0;

        // ---- S = Q @ K^T, pipelined LDSM ----
        float sc[16][4];
#pragma unroll
        for (int nt = 0; nt < 16; nt++)
#pragma unroll
            for (int e = 0; e < 4; e++) sc[nt][e] = 0.f;

        uint32_t kr[2][4];
        LDSM_X4(kr[0][0], kr[0][1], kr[0][2], kr[0][3],
                Kbuf + swz256(k_rowb, k_chb));
#pragma unroll
        for (int np = 0; np < 8; np++) {
#pragma unroll
            for (int kt = 0; kt < 8; kt++) {
                const int idx = np * 8 + kt;
                const int cur = idx & 1, nxt = cur ^ 1;
                if (idx < 63) {
                    const int ni = idx + 1;
                    const uint32_t nrow = (uint32_t)(ni >> 3) * 16 + k_rowb;
                    const uint32_t nch  = (uint32_t)(ni & 7) * 2 + k_chb;
                    LDSM_X4(kr[nxt][0], kr[nxt][1], kr[nxt][2], kr[nxt][3],
                            Kbuf + swz256(nrow, nch));
                }
                MMA16816(sc[2 * np],     qf[kt], kr[cur][0], kr[cur][1]);
                MMA16816(sc[2 * np + 1], qf[kt], kr[cur][2], kr[cur][3]);
            }
        }

        // causal mask (scores already in log2 domain; only diagonal block)
        if (kb == qb) {
#pragma unroll
            for (int nt = 0; nt < 16; nt++) {
                int c0 = kb * 128 + nt * 8 + 2 * tig;
                if (c0     > grA) sc[nt][0] = NEG_BIG;
                if (c0 + 1 > grA) sc[nt][1] = NEG_BIG;
                if (c0     > grB) sc[nt][2] = NEG_BIG;
                if (c0 + 1 > grB) sc[nt][3] = NEG_BIG;
            }
        }

        // online softmax in base-2
        float mAn = NEG_BIG, mBn = NEG_BIG;
#pragma unroll
        for (int nt = 0; nt < 16; nt++) {
            mAn = fmaxf(mAn, fmaxf(sc[nt][0], sc[nt][1]));
            mBn = fmaxf(mBn, fmaxf(sc[nt][2], sc[nt][3]));
        }
        mAn = fmaxf(mAn, __shfl_xor_sync(0xffffffffu, mAn, 1));
        mAn = fmaxf(mAn, __shfl_xor_sync(0xffffffffu, mAn, 2));
        mBn = fmaxf(mBn, __shfl_xor_sync(0xffffffffu, mBn, 1));
        mBn = fmaxf(mBn, __shfl_xor_sync(0xffffffffu, mBn, 2));
        float mAnew = fmaxf(mA, mAn);
        float mBnew = fmaxf(mB, mBn);
        float corrA = ex2f(mA - mAnew);
        float corrB = ex2f(mB - mBnew);
        mA = mAnew; mB = mBnew;

        float lAs = 0.f, lBs = 0.f;
#pragma unroll
        for (int nt = 0; nt < 16; nt++) {
            sc[nt][0] = ex2f(sc[nt][0] - mA);
            sc[nt][1] = ex2f(sc[nt][1] - mA);
            sc[nt][2] = ex2f(sc[nt][2] - mB);
            sc[nt][3] = ex2f(sc[nt][3] - mB);
            lAs += sc[nt][0] + sc[nt][1];
            lBs += sc[nt][2] + sc[nt][3];
        }
        lAs += __shfl_xor_sync(0xffffffffu, lAs, 1);
        lAs += __shfl_xor_sync(0xffffffffu, lAs, 2);
        lBs += __shfl_xor_sync(0xffffffffu, lBs, 1);
        lBs += __shfl_xor_sync(0xffffffffu, lBs, 2);
        lA = lA * corrA + lAs;
        lB = lB * corrB + lBs;

#pragma unroll
        for (int nt = 0; nt < 16; nt++) {
            ob[nt][0] *= corrA; ob[nt][1] *= corrA;
            ob[nt][2] *= corrB; ob[nt][3] *= corrB;
        }

        // P fragments
        uint32_t pa[8][4];
#pragma unroll
        for (int kt = 0; kt < 8; kt++) {
            pa[kt][0] = packh2(sc[2 * kt][0],     sc[2 * kt][1]);
            pa[kt][1] = packh2(sc[2 * kt][2],     sc[2 * kt][3]);
            pa[kt][2] = packh2(sc[2 * kt + 1][0], sc[2 * kt + 1][1]);
            pa[kt][3] = packh2(sc[2 * kt + 1][2], sc[2 * kt + 1][3]);
        }

        // ---- O += P @ V, pipelined LDSM_T ----
        uint32_t vr[2][4];
        LDSM_X4_T(vr[0][0], vr[0][1], vr[0][2], vr[0][3],
                  Vbuf + swz256(v_rowb, v_chb));
#pragma unroll
        for (int np = 0; np < 8; np++) {
#pragma unroll
            for (int kt = 0; kt < 8; kt++) {
                const int idx = np * 8 + kt;
                const int cur = idx & 1, nxt = cur ^ 1;
                if (idx < 63) {
                    const int ni = idx + 1;
                    const uint32_t nrow = (uint32_t)(ni & 7) * 16 + v_rowb;
                    const uint32_t nch  = (uint32_t)(ni >> 3) * 2 + v_chb;
                    LDSM_X4_T(vr[nxt][0], vr[nxt][1], vr[nxt][2], vr[nxt][3],
                              Vbuf + swz256(nrow, nch));
                }
                MMA16816(ob[2 * np],     pa[kt], vr[cur][0], vr[cur][1]);
                MMA16816(ob[2 * np + 1], pa[kt], vr[cur][2], vr[cur][3]);
            }
        }
    }

    // normalize + store
    const float invA = 1.f / lA;
    const float invB = 1.f / lB;
    const size_t rowA = (qrowg + wq * 16 + g) * D_OUTC + h * HDIM;
#pragma unroll
    for (int nt = 0; nt < 16; nt++) {
        int col = nt * 8 + 2 * tig;
        *(uint32_t*)(ctxh + rowA + col) =
            packh2(ob[nt][0] * invA, ob[nt][1] * invA);
        *(uint32_t*)(ctxh + rowA + 8 * D_OUTC + col) =
            packh2(ob[nt][2] * invB, ob[nt][3] * invB);
    }
}

// ---------------------------------------------------------------------------
// Conversions
// ---------------------------------------------------------------------------
__global__ void conv_f2h_kernel(const float* __restrict__ in,
                                __half* __restrict__ out, int n)
{
    int i = (blockIdx.x * 256 + threadIdx.x) * 4;
    if (i < n) {
        float4 v = *reinterpret_cast<const float4*>(in + i);
        __half2* o = reinterpret_cast<__half2*>(out + i);
        o[0] = __floats2half2_rn(v.x, v.y);
        o[1] = __floats2half2_rn(v.z, v.w);
    }
}

__global__ void transpose_cvt_kernel(const float* __restrict__ in,
                                     __half* __restrict__ out, int R, int C)
{
    __shared__ float t[32][33];
    int bx = blockIdx.x * 32, by = blockIdx.y * 32;
#pragma unroll
    for (int i = 0; i < 32; i += 8)
        t[threadIdx.y + i][threadIdx.x] =
            in[(size_t)(by + threadIdx.y + i) * C + bx + threadIdx.x];
    __syncthreads();
#pragma unroll
    for (int i = 0; i < 32; i += 8)
        out[(size_t)(bx + threadIdx.y + i) * R + by + threadIdx.x] =
            __float2half_rn(t[threadIdx.x][threadIdx.y + i]);
}

// ---------------------------------------------------------------------------
// Launch  (ordered so ncu's capture slot lands on the fused projection GEMM)
// ---------------------------------------------------------------------------
extern "C" void kernel_launch(void* const* d_in, const int* in_sizes, int n_in,
                              void* d_out, int out_size)
{
    const float* x    = (const float*)d_in[0];
    const float* Wq   = (const float*)d_in[1];
    const float* Wdkv = (const float*)d_in[2];
    const float* Wukv = (const float*)d_in[3];
    const float* Wout = (const float*)d_in[4];
    const float* bout = (const float*)d_in[5];
    float* out = (float*)d_out;

    __half *xh, *qh, *lath, *kvh, *ctxh, *wqdT, *wukvT, *woutT;
    cudaGetSymbolAddress((void**)&xh,    g_xh);
    cudaGetSymbolAddress((void**)&qh,    g_qh);
    cudaGetSymbolAddress((void**)&lath,  g_lath);
    cudaGetSymbolAddress((void**)&kvh,   g_kvh);
    cudaGetSymbolAddress((void**)&ctxh,  g_ctxh);
    cudaGetSymbolAddress((void**)&wqdT,  g_wqdT);
    cudaGetSymbolAddress((void**)&wukvT, g_wukvT);
    cudaGetSymbolAddress((void**)&woutT, g_woutT);

    cudaFuncSetAttribute(gemm_h_kernel,
                         cudaFuncAttributeMaxDynamicSharedMemorySize, GEMM_SMEM);
    cudaFuncSetAttribute(attn_h_kernel,
                         cudaFuncAttributeMaxDynamicSharedMemorySize, ATTN_SMEM);

    dim3 tb(32, 8);

    // #0: x -> fp16
    conv_f2h_kernel<<<(MTOT * D_INC) / 1024, 256>>>(x, xh, MTOT * D_INC);
    // #1, #2: Wq|Wdkv -> stacked transposed fp16
    transpose_cvt_kernel<<<dim3(D_OUTC / 32, D_INC / 32), tb>>>(Wq, wqdT, D_INC, D_OUTC);
    transpose_cvt_kernel<<<dim3(LATENT / 32, D_INC / 32), tb>>>(
        Wdkv, wqdT + (size_t)D_OUTC * D_INC, D_INC, LATENT);

    // #3: [q*scale | latent] = x @ [Wq | Wdkv]
    gemm_h_kernel<<<dim3((D_OUTC + LATENT) / 256, MTOT / 128), 256, GEMM_SMEM>>>(
        xh, wqdT, nullptr, qh, D_OUTC, lath, LATENT, D_OUTC,
        D_INC, D_INC, D_INC, 0, QK_SCALE);

    // #4: Wukv transpose
    transpose_cvt_kernel<<<dim3((2 * D_OUTC) / 32, LATENT / 32), tb>>>(Wukv, wukvT, LATENT, 2 * D_OUTC);

    // #5: kv = latent @ Wukv
    gemm_h_kernel<<<dim3((2 * D_OUTC) / 256, MTOT / 128), 256, GEMM_SMEM>>>(
        lath, wukvT, nullptr, kvh, 2 * D_OUTC, nullptr, 0, 1 << 30,
        LATENT, LATENT, LATENT, 0, 1.0f);

    // #6: Wout transpose
    transpose_cvt_kernel<<<dim3(D_INC / 32, D_OUTC / 32), tb>>>(Wout, woutT, D_OUTC, D_INC);

    // #7: attention -> ctx
    attn_h_kernel<<<dim3(SEQ / 128, NHEADS, BATCH), 256, ATTN_SMEM>>>(qh, kvh, ctxh);

    // #8: out = ctx @ Wout + b  (fp32)
    gemm_h_kernel<<<dim3(D_INC / 256, MTOT / 128), 256, GEMM_SMEM>>>(
        ctxh, woutT, bout, out, D_INC, nullptr, 0, 1 << 30,
        D_OUTC, D_OUTC, D_OUTC, 1, 1.0f);
}

// round 6
// speedup vs baseline: 8.0704x; 1.0163x over previous
#include <cuda_runtime.h>
#include <cuda_fp16.h>
#include <cstdint>
#include <math.h>

// Problem constants
#define D_INC   2048
#define D_OUTC  2048
#define NHEADS  16
#define HDIM    128
#define LATENT  256
#define BATCH   2
#define SEQ     2048
#define MTOT    (BATCH * SEQ)        // 4096

#define NEG_BIG (-1.0e30f)
// rsqrt(128) * log2(e)  — folded into q projection; softmax uses ex2
#define QK_SCALE 0.12751875732f

// ---------------------------------------------------------------------------
// Scratch (device globals; no allocation allowed)
// ---------------------------------------------------------------------------
__device__ __align__(16) __half g_xh  [(size_t)MTOT * D_INC];
__device__ __align__(16) __half g_qh  [(size_t)MTOT * D_OUTC];
__device__ __align__(16) __half g_lath[(size_t)MTOT * LATENT];
__device__ __align__(16) __half g_kvh [(size_t)MTOT * 2 * D_OUTC];
__device__ __align__(16) __half g_ctxh[(size_t)MTOT * D_OUTC];
__device__ __align__(16) __half g_wqdT [(size_t)(D_OUTC + LATENT) * D_INC];
__device__ __align__(16) __half g_wukvT[(size_t)(2 * D_OUTC) * LATENT];
__device__ __align__(16) __half g_woutT[(size_t)D_INC * D_OUTC];

// ---------------------------------------------------------------------------
// PTX helpers
// ---------------------------------------------------------------------------
__device__ __forceinline__ uint32_t smem_u32(const void* p) {
    uint32_t a;
    asm("{ .reg .u64 t; cvta.to.shared.u64 t, %1; cvt.u32.u64 %0, t; }"
        : "=r"(a) : "l"(p));
    return a;
}
__device__ __forceinline__ float ex2f(float x) {
    float y;
    asm("ex2.approx.f32 %0, %1;" : "=f"(y) : "f"(x));
    return y;
}

#define CP_ASYNC16(dst, src) \
    asm volatile("cp.async.cg.shared.global [%0], [%1], 16;" \
                 :: "r"(dst), "l"(src) : "memory")
#define CP_COMMIT() asm volatile("cp.async.commit_group;" ::: "memory")
#define CP_WAIT1()  asm volatile("cp.async.wait_group 1;" ::: "memory")

#define LDSM_X4(r0, r1, r2, r3, a) \
    asm volatile("ldmatrix.sync.aligned.m8n8.x4.shared.b16 {%0,%1,%2,%3}, [%4];" \
                 : "=r"(r0), "=r"(r1), "=r"(r2), "=r"(r3) : "r"(a))
#define LDSM_X4_T(r0, r1, r2, r3, a) \
    asm volatile("ldmatrix.sync.aligned.m8n8.x4.trans.shared.b16 {%0,%1,%2,%3}, [%4];" \
                 : "=r"(r0), "=r"(r1), "=r"(r2), "=r"(r3) : "r"(a))

#define MMA16816(d, a, b0_, b1_) \
    asm volatile("mma.sync.aligned.m16n8k16.row.col.f32.f16.f16.f32 " \
                 "{%0,%1,%2,%3}, {%4,%5,%6,%7}, {%8,%9}, {%0,%1,%2,%3};" \
                 : "+f"((d)[0]), "+f"((d)[1]), "+f"((d)[2]), "+f"((d)[3]) \
                 : "r"((a)[0]), "r"((a)[1]), "r"((a)[2]), "r"((a)[3]), \
                   "r"(b0_), "r"(b1_))

__device__ __forceinline__ uint32_t swz128(uint32_t r, uint32_t c) {
    return r * 128u + ((c ^ (r & 7u)) << 4);
}
__device__ __forceinline__ uint32_t swz256(uint32_t r, uint32_t c) {
    return r * 256u + ((c ^ (r & 7u)) << 4);
}
__device__ __forceinline__ uint32_t packh2(float a, float b) {
    __half2 h = __floats2half2_rn(a, b);
    return *reinterpret_cast<uint32_t*>(&h);
}

// ---------------------------------------------------------------------------
// fp16 GEMM: C[M,N] = A[M,K] @ Bt[N,K]^T
// CTA 128(M) x 128(N), BK=64, 8 warps (4M x 2N), warp tile 32x64.
// 3-stage cp.async pipeline (32KB/stage, 96KB total) -> 2 CTAs/SM.
// __launch_bounds__(256, 2): regs capped at 128 so two CTAs co-reside;
// inter-phase gaps (barrier/epilogue/prologue) hidden by the sibling CTA.
// ---------------------------------------------------------------------------
#define GSTAGE     32768
#define GEMM_SMEM  (3 * GSTAGE + 1024)

__device__ __forceinline__ void gemm_load_stage(
    uint32_t buf, const __half* __restrict__ A, const __half* __restrict__ Bt,
    int lda, int ldb, int m0, int n0, int k0, int tid)
{
    const uint32_t bufA = buf, bufB = buf + 16384;
#pragma unroll
    for (int i = 0; i < 4; i++) {            // A: 128 rows x 8 chunks
        int f = tid + i * 256;
        int r = f >> 3, c = f & 7;
        CP_ASYNC16(bufA + swz128(r, c),
                   A + (size_t)(m0 + r) * lda + k0 + c * 8);
    }
#pragma unroll
    for (int i = 0; i < 4; i++) {            // B: 128 rows x 8 chunks
        int f = tid + i * 256;
        int r = f >> 3, c = f & 7;
        CP_ASYNC16(bufB + swz128(r, c),
                   Bt + (size_t)(n0 + r) * ldb + k0 + c * 8);
    }
}

__global__ __launch_bounds__(256, 2)
void gemm_h_kernel(const __half* __restrict__ A, const __half* __restrict__ Bt,
                   const float* __restrict__ bias,
                   void* __restrict__ Cv, int ldc,
                   void* __restrict__ C2v, int ldc2, int nsplit,
                   int K, int lda, int ldb, int fp32out, float cscale)
{
    extern __shared__ char smem_raw[];
    uint32_t sb = (smem_u32(smem_raw) + 1023u) & ~1023u;

    const int tid  = threadIdx.x;
    const int wid  = tid >> 5;
    const int lane = tid & 31;
    const int wm   = wid & 3;        // 4 M quarters of 32 rows
    const int wn   = wid >> 2;       // 2 N halves of 64 cols
    const int g    = lane >> 2;
    const int tig  = lane & 3;
    const int m0 = blockIdx.y * 128;
    const int n0 = blockIdx.x * 128;

    float acc[2][8][4];
#pragma unroll
    for (int mt = 0; mt < 2; mt++)
#pragma unroll
        for (int nt = 0; nt < 8; nt++)
#pragma unroll
            for (int e = 0; e < 4; e++) acc[mt][nt][e] = 0.f;

    const uint32_t a_row = wm * 32 + (lane & 15);
    const uint32_t a_chb = lane >> 4;
    const uint32_t b_row = wn * 64 + ((lane >> 4) << 3) + (lane & 7);
    const uint32_t b_chb = (lane >> 3) & 1;

    const int S = K >> 6;

    gemm_load_stage(sb,          A, Bt, lda, ldb, m0, n0, 0,  tid); CP_COMMIT();
    gemm_load_stage(sb + GSTAGE, A, Bt, lda, ldb, m0, n0, 64, tid); CP_COMMIT();

    for (int s = 0; s < S; s++) {
        CP_WAIT1();                  // stage s resident (newest in-flight: s+1)
        __syncthreads();             // all warps done reading stage s-1
        if (s + 2 < S) {             // buffer (s+2)%3 == (s-1)%3, now free
            int bi = s + 2 - 3 * ((s + 2) / 3);
            gemm_load_stage(sb + bi * GSTAGE,
                            A, Bt, lda, ldb, m0, n0, (s + 2) * 64, tid);
        }
        CP_COMMIT();

        const int sbi = s - 3 * (s / 3);
        const uint32_t bA = sb + sbi * GSTAGE;
        const uint32_t bB = bA + 16384;

#pragma unroll
        for (int kt = 0; kt < 4; kt++) {
            uint32_t af[2][4], bf[8][2];
            const uint32_t ch = kt * 2;
#pragma unroll
            for (int mt = 0; mt < 2; mt++)
                LDSM_X4(af[mt][0], af[mt][1], af[mt][2], af[mt][3],
                        bA + swz128(a_row + mt * 16, ch + a_chb));
#pragma unroll
            for (int np = 0; np < 4; np++) {
                uint32_t r0, r1, r2, r3;
                LDSM_X4(r0, r1, r2, r3, bB + swz128(b_row + np * 16, ch + b_chb));
                bf[2 * np][0] = r0; bf[2 * np][1] = r1;
                bf[2 * np + 1][0] = r2; bf[2 * np + 1][1] = r3;
            }
#pragma unroll
            for (int mt = 0; mt < 2; mt++)
#pragma unroll
                for (int nt = 0; nt < 8; nt++)
                    MMA16816(acc[mt][nt], af[mt], bf[nt][0], bf[nt][1]);
        }
    }

    // Epilogue
#pragma unroll
    for (int mt = 0; mt < 2; mt++) {
#pragma unroll
        for (int nt = 0; nt < 8; nt++) {
            int row = m0 + wm * 32 + mt * 16 + g;
            int col = n0 + wn * 64 + nt * 8 + 2 * tig;
            float* a = acc[mt][nt];
            if (fp32out) {
                float* C = (float*)Cv;
                float b0 = bias ? bias[col]     : 0.f;
                float b1 = bias ? bias[col + 1] : 0.f;
                *(float2*)(C + (size_t)row * ldc + col) =
                    make_float2(a[0] + b0, a[1] + b1);
                *(float2*)(C + (size_t)(row + 8) * ldc + col) =
                    make_float2(a[2] + b0, a[3] + b1);
            } else if (col < nsplit) {
                __half* C = (__half*)Cv;
                *(uint32_t*)(C + (size_t)row * ldc + col) =
                    packh2(a[0] * cscale, a[1] * cscale);
                *(uint32_t*)(C + (size_t)(row + 8) * ldc + col) =
                    packh2(a[2] * cscale, a[3] * cscale);
            } else {
                __half* C = (__half*)C2v;
                int c2 = col - nsplit;
                *(uint32_t*)(C + (size_t)row * ldc2 + c2)       = packh2(a[0], a[1]);
                *(uint32_t*)(C + (size_t)(row + 8) * ldc2 + c2) = packh2(a[2], a[3]);
            }
        }
    }
}

// ---------------------------------------------------------------------------
// Flash attention, fp16 mma.sync, causal. BQ=128, BK=128, 8 warps x 16 rows.
// q pre-scaled by rsqrt(128)*log2(e); softmax uses ex2.
// smem: Q 32KB + 2 stages x (K 32KB + V 32KB) = 160KB.
// ---------------------------------------------------------------------------
#define ATTN_SMEM (163840 + 1024)

__global__ __launch_bounds__(256, 1)
void attn_h_kernel(const __half* __restrict__ qh, const __half* __restrict__ kvh,
                   __half* __restrict__ ctxh)
{
    extern __shared__ char smem_raw[];
    uint32_t sb = (smem_u32(smem_raw) + 1023u) & ~1023u;
    const uint32_t Qs  = sb;
    const uint32_t KB0 = sb + 32768;
    const uint32_t VB0 = sb + 65536;
    const uint32_t KB1 = sb + 98304;
    const uint32_t VB1 = sb + 131072;

    const int tid  = threadIdx.x;
    const int wq   = tid >> 5;
    const int lane = tid & 31;
    const int g    = lane >> 2;
    const int tig  = lane & 3;
    const int qb = gridDim.x - 1 - blockIdx.x;
    const int h  = blockIdx.y;
    const int b  = blockIdx.z;

    const int qrow0 = qb * 128;
    const size_t qrowg  = (size_t)b * SEQ + qrow0;
    const size_t kvrowg = (size_t)b * SEQ;

#pragma unroll
    for (int i = 0; i < 8; i++) {
        int f = tid + i * 256;
        int r = f >> 4, c = f & 15;
        CP_ASYNC16(Qs + swz256(r, c),
                   qh + (qrowg + r) * D_OUTC + h * HDIM + c * 8);
        const __half* src = kvh + (kvrowg + r) * (2 * D_OUTC) + h * HDIM + c * 8;
        CP_ASYNC16(KB0 + swz256(r, c), src);
        CP_ASYNC16(VB0 + swz256(r, c), src + D_OUTC);
    }
    CP_COMMIT();

    float ob[16][4];
#pragma unroll
    for (int nt = 0; nt < 16; nt++)
#pragma unroll
        for (int e = 0; e < 4; e++) ob[nt][e] = 0.f;
    float mA = NEG_BIG, mB = NEG_BIG, lA = 0.f, lB = 0.f;
    uint32_t qf[8][4];
    const int grA = qrow0 + wq * 16 + g;
    const int grB = grA + 8;

    const uint32_t k_rowb = ((lane >> 4) << 3) + (lane & 7);
    const uint32_t k_chb  = (lane >> 3) & 1;
    const uint32_t v_rowb = (((lane >> 3) & 1) << 3) + (lane & 7);
    const uint32_t v_chb  = lane >> 4;

    for (int kb = 0; kb <= qb; kb++) {
        __syncthreads();
        if (kb + 1 <= qb) {
            const uint32_t nK = ((kb + 1) & 1) ? KB1 : KB0;
            const uint32_t nV = ((kb + 1) & 1) ? VB1 : VB0;
#pragma unroll
            for (int i = 0; i < 8; i++) {
                int f = tid + i * 256;
                int r = f >> 4, c = f & 15;
                const __half* src = kvh + (kvrowg + (size_t)(kb + 1) * 128 + r) * (2 * D_OUTC)
                                    + h * HDIM + c * 8;
                CP_ASYNC16(nK + swz256(r, c), src);
                CP_ASYNC16(nV + swz256(r, c), src + D_OUTC);
            }
        }
        CP_COMMIT();
        CP_WAIT1();
        __syncthreads();

        if (kb == 0) {
#pragma unroll
            for (int kt = 0; kt < 8; kt++) {
                uint32_t row = wq * 16 + (lane & 15);
                uint32_t ch  = kt * 2 + (lane >> 4);
                LDSM_X4(qf[kt][0], qf[kt][1], qf[kt][2], qf[kt][3],
                        Qs + swz256(row, ch));
            }
        }

        const uint32_t Kbuf = (kb & 1) ? KB1 : KB0;
        const uint32_t Vbuf = (kb & 1) ? VB1 : VB0;

        // ---- S = Q @ K^T, pipelined LDSM ----
        float sc[16][4];
#pragma unroll
        for (int nt = 0; nt < 16; nt++)
#pragma unroll
            for (int e = 0; e < 4; e++) sc[nt][e] = 0.f;

        uint32_t kr[2][4];
        LDSM_X4(kr[0][0], kr[0][1], kr[0][2], kr[0][3],
                Kbuf + swz256(k_rowb, k_chb));
#pragma unroll
        for (int np = 0; np < 8; np++) {
#pragma unroll
            for (int kt = 0; kt < 8; kt++) {
                const int idx = np * 8 + kt;
                const int cur = idx & 1, nxt = cur ^ 1;
                if (idx < 63) {
                    const int ni = idx + 1;
                    const uint32_t nrow = (uint32_t)(ni >> 3) * 16 + k_rowb;
                    const uint32_t nch  = (uint32_t)(ni & 7) * 2 + k_chb;
                    LDSM_X4(kr[nxt][0], kr[nxt][1], kr[nxt][2], kr[nxt][3],
                            Kbuf + swz256(nrow, nch));
                }
                MMA16816(sc[2 * np],     qf[kt], kr[cur][0], kr[cur][1]);
                MMA16816(sc[2 * np + 1], qf[kt], kr[cur][2], kr[cur][3]);
            }
        }

        if (kb == qb) {
#pragma unroll
            for (int nt = 0; nt < 16; nt++) {
                int c0 = kb * 128 + nt * 8 + 2 * tig;
                if (c0     > grA) sc[nt][0] = NEG_BIG;
                if (c0 + 1 > grA) sc[nt][1] = NEG_BIG;
                if (c0     > grB) sc[nt][2] = NEG_BIG;
                if (c0 + 1 > grB) sc[nt][3] = NEG_BIG;
            }
        }

        float mAn = NEG_BIG, mBn = NEG_BIG;
#pragma unroll
        for (int nt = 0; nt < 16; nt++) {
            mAn = fmaxf(mAn, fmaxf(sc[nt][0], sc[nt][1]));
            mBn = fmaxf(mBn, fmaxf(sc[nt][2], sc[nt][3]));
        }
        mAn = fmaxf(mAn, __shfl_xor_sync(0xffffffffu, mAn, 1));
        mAn = fmaxf(mAn, __shfl_xor_sync(0xffffffffu, mAn, 2));
        mBn = fmaxf(mBn, __shfl_xor_sync(0xffffffffu, mBn, 1));
        mBn = fmaxf(mBn, __shfl_xor_sync(0xffffffffu, mBn, 2));
        float mAnew = fmaxf(mA, mAn);
        float mBnew = fmaxf(mB, mBn);
        float corrA = ex2f(mA - mAnew);
        float corrB = ex2f(mB - mBnew);
        mA = mAnew; mB = mBnew;

        float lAs = 0.f, lBs = 0.f;
#pragma unroll
        for (int nt = 0; nt < 16; nt++) {
            sc[nt][0] = ex2f(sc[nt][0] - mA);
            sc[nt][1] = ex2f(sc[nt][1] - mA);
            sc[nt][2] = ex2f(sc[nt][2] - mB);
            sc[nt][3] = ex2f(sc[nt][3] - mB);
            lAs += sc[nt][0] + sc[nt][1];
            lBs += sc[nt][2] + sc[nt][3];
        }
        lAs += __shfl_xor_sync(0xffffffffu, lAs, 1);
        lAs += __shfl_xor_sync(0xffffffffu, lAs, 2);
        lBs += __shfl_xor_sync(0xffffffffu, lBs, 1);
        lBs += __shfl_xor_sync(0xffffffffu, lBs, 2);
        lA = lA * corrA + lAs;
        lB = lB * corrB + lBs;

#pragma unroll
        for (int nt = 0; nt < 16; nt++) {
            ob[nt][0] *= corrA; ob[nt][1] *= corrA;
            ob[nt][2] *= corrB; ob[nt][3] *= corrB;
        }

        uint32_t pa[8][4];
#pragma unroll
        for (int kt = 0; kt < 8; kt++) {
            pa[kt][0] = packh2(sc[2 * kt][0],     sc[2 * kt][1]);
            pa[kt][1] = packh2(sc[2 * kt][2],     sc[2 * kt][3]);
            pa[kt][2] = packh2(sc[2 * kt + 1][0], sc[2 * kt + 1][1]);
            pa[kt][3] = packh2(sc[2 * kt + 1][2], sc[2 * kt + 1][3]);
        }

        uint32_t vr[2][4];
        LDSM_X4_T(vr[0][0], vr[0][1], vr[0][2], vr[0][3],
                  Vbuf + swz256(v_rowb, v_chb));
#pragma unroll
        for (int np = 0; np < 8; np++) {
#pragma unroll
            for (int kt = 0; kt < 8; kt++) {
                const int idx = np * 8 + kt;
                const int cur = idx & 1, nxt = cur ^ 1;
                if (idx < 63) {
                    const int ni = idx + 1;
                    const uint32_t nrow = (uint32_t)(ni & 7) * 16 + v_rowb;
                    const uint32_t nch  = (uint32_t)(ni >> 3) * 2 + v_chb;
                    LDSM_X4_T(vr[nxt][0], vr[nxt][1], vr[nxt][2], vr[nxt][3],
                              Vbuf + swz256(nrow, nch));
                }
                MMA16816(ob[2 * np],     pa[kt], vr[cur][0], vr[cur][1]);
                MMA16816(ob[2 * np + 1], pa[kt], vr[cur][2], vr[cur][3]);
            }
        }
    }

    const float invA = 1.f / lA;
    const float invB = 1.f / lB;
    const size_t rowA = (qrowg + wq * 16 + g) * D_OUTC + h * HDIM;
#pragma unroll
    for (int nt = 0; nt < 16; nt++) {
        int col = nt * 8 + 2 * tig;
        *(uint32_t*)(ctxh + rowA + col) =
            packh2(ob[nt][0] * invA, ob[nt][1] * invA);
        *(uint32_t*)(ctxh + rowA + 8 * D_OUTC + col) =
            packh2(ob[nt][2] * invB, ob[nt][3] * invB);
    }
}

// ---------------------------------------------------------------------------
// Conversions
// ---------------------------------------------------------------------------
__global__ void conv_f2h_kernel(const float* __restrict__ in,
                                __half* __restrict__ out, int n)
{
    int i = (blockIdx.x * 256 + threadIdx.x) * 4;
    if (i < n) {
        float4 v = *reinterpret_cast<const float4*>(in + i);
        __half2* o = reinterpret_cast<__half2*>(out + i);
        o[0] = __floats2half2_rn(v.x, v.y);
        o[1] = __floats2half2_rn(v.z, v.w);
    }
}

__global__ void transpose_cvt_kernel(const float* __restrict__ in,
                                     __half* __restrict__ out, int R, int C)
{
    __shared__ float t[32][33];
    int bx = blockIdx.x * 32, by = blockIdx.y * 32;
#pragma unroll
    for (int i = 0; i < 32; i += 8)
        t[threadIdx.y + i][threadIdx.x] =
            in[(size_t)(by + threadIdx.y + i) * C + bx + threadIdx.x];
    __syncthreads();
#pragma unroll
    for (int i = 0; i < 32; i += 8)
        out[(size_t)(bx + threadIdx.y + i) * R + by + threadIdx.x] =
            __float2half_rn(t[threadIdx.x][threadIdx.y + i]);
}

// ---------------------------------------------------------------------------
// Launch (capture slot #3 = fused projection GEMM)
// ---------------------------------------------------------------------------
extern "C" void kernel_launch(void* const* d_in, const int* in_sizes, int n_in,
                              void* d_out, int out_size)
{
    const float* x    = (const float*)d_in[0];
    const float* Wq   = (const float*)d_in[1];
    const float* Wdkv = (const float*)d_in[2];
    const float* Wukv = (const float*)d_in[3];
    const float* Wout = (const float*)d_in[4];
    const float* bout = (const float*)d_in[5];
    float* out = (float*)d_out;

    __half *xh, *qh, *lath, *kvh, *ctxh, *wqdT, *wukvT, *woutT;
    cudaGetSymbolAddress((void**)&xh,    g_xh);
    cudaGetSymbolAddress((void**)&qh,    g_qh);
    cudaGetSymbolAddress((void**)&lath,  g_lath);
    cudaGetSymbolAddress((void**)&kvh,   g_kvh);
    cudaGetSymbolAddress((void**)&ctxh,  g_ctxh);
    cudaGetSymbolAddress((void**)&wqdT,  g_wqdT);
    cudaGetSymbolAddress((void**)&wukvT, g_wukvT);
    cudaGetSymbolAddress((void**)&woutT, g_woutT);

    cudaFuncSetAttribute(gemm_h_kernel,
                         cudaFuncAttributeMaxDynamicSharedMemorySize, GEMM_SMEM);
    cudaFuncSetAttribute(attn_h_kernel,
                         cudaFuncAttributeMaxDynamicSharedMemorySize, ATTN_SMEM);

    dim3 tb(32, 8);

    // #0: x -> fp16
    conv_f2h_kernel<<<(MTOT * D_INC) / 1024, 256>>>(x, xh, MTOT * D_INC);
    // #1, #2: Wq|Wdkv -> stacked transposed fp16
    transpose_cvt_kernel<<<dim3(D_OUTC / 32, D_INC / 32), tb>>>(Wq, wqdT, D_INC, D_OUTC);
    transpose_cvt_kernel<<<dim3(LATENT / 32, D_INC / 32), tb>>>(
        Wdkv, wqdT + (size_t)D_OUTC * D_INC, D_INC, LATENT);

    // #3: [q*scale | latent] = x @ [Wq | Wdkv]
    gemm_h_kernel<<<dim3((D_OUTC + LATENT) / 128, MTOT / 128), 256, GEMM_SMEM>>>(
        xh, wqdT, nullptr, qh, D_OUTC, lath, LATENT, D_OUTC,
        D_INC, D_INC, D_INC, 0, QK_SCALE);

    // #4: Wukv transpose
    transpose_cvt_kernel<<<dim3((2 * D_OUTC) / 32, LATENT / 32), tb>>>(Wukv, wukvT, LATENT, 2 * D_OUTC);

    // #5: kv = latent @ Wukv
    gemm_h_kernel<<<dim3((2 * D_OUTC) / 128, MTOT / 128), 256, GEMM_SMEM>>>(
        lath, wukvT, nullptr, kvh, 2 * D_OUTC, nullptr, 0, 1 << 30,
        LATENT, LATENT, LATENT, 0, 1.0f);

    // #6: Wout transpose
    transpose_cvt_kernel<<<dim3(D_INC / 32, D_OUTC / 32), tb>>>(Wout, woutT, D_OUTC, D_INC);

    // #7: attention -> ctx
    attn_h_kernel<<<dim3(SEQ / 128, NHEADS, BATCH), 256, ATTN_SMEM>>>(qh, kvh, ctxh);

    // #8: out = ctx @ Wout + b  (fp32)
    gemm_h_kernel<<<dim3(D_INC / 128, MTOT / 128), 256, GEMM_SMEM>>>(
        ctxh, woutT, bout, out, D_INC, nullptr, 0, 1 << 30,
        D_OUTC, D_OUTC, D_OUTC, 1, 1.0f);
}

// round 7
// speedup vs baseline: 8.5058x; 1.0540x over previous
#include <cuda_runtime.h>
#include <cuda_fp16.h>
#include <cstdint>
#include <math.h>

// Problem constants
#define D_INC   2048
#define D_OUTC  2048
#define NHEADS  16
#define HDIM    128
#define LATENT  256
#define BATCH   2
#define SEQ     2048
#define MTOT    (BATCH * SEQ)        // 4096

#define NEG_BIG (-1.0e30f)
// rsqrt(128) * log2(e)  — folded into q projection; softmax uses ex2
#define QK_SCALE 0.12751875732f
#define H2_ONES  0x3C003C00u

// ---------------------------------------------------------------------------
// Scratch (device globals; no allocation allowed)
// ---------------------------------------------------------------------------
__device__ __align__(16) __half g_xh  [(size_t)MTOT * D_INC];
__device__ __align__(16) __half g_qh  [(size_t)MTOT * D_OUTC];
__device__ __align__(16) __half g_lath[(size_t)MTOT * LATENT];
__device__ __align__(16) __half g_kvh [(size_t)MTOT * 2 * D_OUTC];
__device__ __align__(16) __half g_ctxh[(size_t)MTOT * D_OUTC];
__device__ __align__(16) __half g_wqd [(size_t)D_INC * (D_OUTC + LATENT)];  // [2048][2304]
__device__ __align__(16) __half g_wukv[(size_t)LATENT * 2 * D_OUTC];        // [256][4096]
__device__ __align__(16) __half g_wout[(size_t)D_OUTC * D_INC];             // [2048][2048]

// ---------------------------------------------------------------------------
// PTX helpers
// ---------------------------------------------------------------------------
__device__ __forceinline__ uint32_t smem_u32(const void* p) {
    uint32_t a;
    asm("{ .reg .u64 t; cvta.to.shared.u64 t, %1; cvt.u32.u64 %0, t; }"
        : "=r"(a) : "l"(p));
    return a;
}
__device__ __forceinline__ float ex2f(float x) {
    float y;
    asm("ex2.approx.f32 %0, %1;" : "=f"(y) : "f"(x));
    return y;
}
__device__ __forceinline__ uint32_t h2ex2(uint32_t x) {
    uint32_t y;
    asm("ex2.approx.f16x2 %0, %1;" : "=r"(y) : "r"(x));
    return y;
}

#define CP_ASYNC16(dst, src) \
    asm volatile("cp.async.cg.shared.global [%0], [%1], 16;" \
                 :: "r"(dst), "l"(src) : "memory")
#define CP_COMMIT() asm volatile("cp.async.commit_group;" ::: "memory")
#define CP_WAIT1()  asm volatile("cp.async.wait_group 1;" ::: "memory")

#define LDSM_X4(r0, r1, r2, r3, a) \
    asm volatile("ldmatrix.sync.aligned.m8n8.x4.shared.b16 {%0,%1,%2,%3}, [%4];" \
                 : "=r"(r0), "=r"(r1), "=r"(r2), "=r"(r3) : "r"(a))
#define LDSM_X4_T(r0, r1, r2, r3, a) \
    asm volatile("ldmatrix.sync.aligned.m8n8.x4.trans.shared.b16 {%0,%1,%2,%3}, [%4];" \
                 : "=r"(r0), "=r"(r1), "=r"(r2), "=r"(r3) : "r"(a))

#define MMA16816(d, a, b0_, b1_) \
    asm volatile("mma.sync.aligned.m16n8k16.row.col.f32.f16.f16.f32 " \
                 "{%0,%1,%2,%3}, {%4,%5,%6,%7}, {%8,%9}, {%0,%1,%2,%3};" \
                 : "+f"((d)[0]), "+f"((d)[1]), "+f"((d)[2]), "+f"((d)[3]) \
                 : "r"((a)[0]), "r"((a)[1]), "r"((a)[2]), "r"((a)[3]), \
                   "r"(b0_), "r"(b1_))

__device__ __forceinline__ uint32_t swz128(uint32_t r, uint32_t c) {
    return r * 128u + ((c ^ (r & 7u)) << 4);
}
__device__ __forceinline__ uint32_t swz256(uint32_t r, uint32_t c) {
    return r * 256u + ((c ^ (r & 7u)) << 4);
}
__device__ __forceinline__ uint32_t packh2(float a, float b) {
    __half2 h = __floats2half2_rn(a, b);
    return *reinterpret_cast<uint32_t*>(&h);
}

// ---------------------------------------------------------------------------
// fp16 GEMM: C[M,N] = A[M,K] @ B[K,N]   (B row-major [K][N], trans-ldmatrix)
// CTA 128(M) x 128(N), BK=64, 8 warps (4M x 2N), warp tile 32x64.
// 3-stage cp.async pipeline (32KB/stage) -> 2 CTAs/SM (regs capped 128).
// Epilogue routes col<nsplit -> C (ldc), else -> C2 (ldc2). fp32out => bias add.
// ---------------------------------------------------------------------------
#define GSTAGE     32768
#define GEMM_SMEM  (3 * GSTAGE + 1024)

__device__ __forceinline__ void gemm_load_stage(
    uint32_t buf, const __half* __restrict__ A, const __half* __restrict__ B,
    int lda, int ldb, int m0, int n0, int k0, int tid)
{
    const uint32_t bufA = buf, bufB = buf + 16384;
#pragma unroll
    for (int i = 0; i < 4; i++) {            // A: 128 m-rows x 8 chunks (128B rows)
        int f = tid + i * 256;
        int r = f >> 3, c = f & 7;
        CP_ASYNC16(bufA + swz128(r, c),
                   A + (size_t)(m0 + r) * lda + k0 + c * 8);
    }
#pragma unroll
    for (int i = 0; i < 4; i++) {            // B: 64 k-rows x 16 chunks (256B rows)
        int f = tid + i * 256;
        int r = f >> 4, c = f & 15;
        CP_ASYNC16(bufB + swz256(r, c),
                   B + (size_t)(k0 + r) * ldb + n0 + c * 8);
    }
}

__global__ __launch_bounds__(256, 2)
void gemm_h_kernel(const __half* __restrict__ A, const __half* __restrict__ B,
                   const float* __restrict__ bias,
                   void* __restrict__ Cv, int ldc,
                   void* __restrict__ C2v, int ldc2, int nsplit,
                   int K, int lda, int ldb, int fp32out, float cscale)
{
    extern __shared__ char smem_raw[];
    uint32_t sb = (smem_u32(smem_raw) + 1023u) & ~1023u;

    const int tid  = threadIdx.x;
    const int wid  = tid >> 5;
    const int lane = tid & 31;
    const int wm   = wid & 3;        // 4 M quarters of 32 rows
    const int wn   = wid >> 2;       // 2 N halves of 64 cols
    const int g    = lane >> 2;
    const int tig  = lane & 3;
    const int m0 = blockIdx.y * 128;
    const int n0 = blockIdx.x * 128;

    float acc[2][8][4];
#pragma unroll
    for (int mt = 0; mt < 2; mt++)
#pragma unroll
        for (int nt = 0; nt < 8; nt++)
#pragma unroll
            for (int e = 0; e < 4; e++) acc[mt][nt][e] = 0.f;

    const uint32_t a_row  = wm * 32 + (lane & 15);
    const uint32_t a_chb  = lane >> 4;
    // trans-B fragment addressing (same pattern as attention V path)
    const uint32_t bt_row = (((lane >> 3) & 1) << 3) + (lane & 7);  // k within 16
    const uint32_t bt_chb = lane >> 4;                               // n-chunk parity

    const int S = K >> 6;

    gemm_load_stage(sb,          A, B, lda, ldb, m0, n0, 0,  tid); CP_COMMIT();
    gemm_load_stage(sb + GSTAGE, A, B, lda, ldb, m0, n0, 64, tid); CP_COMMIT();

    for (int s = 0; s < S; s++) {
        CP_WAIT1();
        __syncthreads();
        if (s + 2 < S) {
            int bi = s + 2 - 3 * ((s + 2) / 3);
            gemm_load_stage(sb + bi * GSTAGE,
                            A, B, lda, ldb, m0, n0, (s + 2) * 64, tid);
        }
        CP_COMMIT();

        const int sbi = s - 3 * (s / 3);
        const uint32_t bA = sb + sbi * GSTAGE;
        const uint32_t bB = bA + 16384;

#pragma unroll
        for (int kt = 0; kt < 4; kt++) {
            uint32_t af[2][4], bf[8][2];
#pragma unroll
            for (int mt = 0; mt < 2; mt++)
                LDSM_X4(af[mt][0], af[mt][1], af[mt][2], af[mt][3],
                        bA + swz128(a_row + mt * 16, kt * 2 + a_chb));
#pragma unroll
            for (int np = 0; np < 4; np++) {
                uint32_t r0, r1, r2, r3;
                LDSM_X4_T(r0, r1, r2, r3,
                          bB + swz256(kt * 16 + bt_row,
                                      (uint32_t)(wn * 8 + np * 2) + bt_chb));
                bf[2 * np][0] = r0; bf[2 * np][1] = r1;
                bf[2 * np + 1][0] = r2; bf[2 * np + 1][1] = r3;
            }
#pragma unroll
            for (int mt = 0; mt < 2; mt++)
#pragma unroll
                for (int nt = 0; nt < 8; nt++)
                    MMA16816(acc[mt][nt], af[mt], bf[nt][0], bf[nt][1]);
        }
    }

    // Epilogue
#pragma unroll
    for (int mt = 0; mt < 2; mt++) {
#pragma unroll
        for (int nt = 0; nt < 8; nt++) {
            int row = m0 + wm * 32 + mt * 16 + g;
            int col = n0 + wn * 64 + nt * 8 + 2 * tig;
            float* a = acc[mt][nt];
            if (fp32out) {
                float* C = (float*)Cv;
                float b0 = bias ? bias[col]     : 0.f;
                float b1 = bias ? bias[col + 1] : 0.f;
                *(float2*)(C + (size_t)row * ldc + col) =
                    make_float2(a[0] + b0, a[1] + b1);
                *(float2*)(C + (size_t)(row + 8) * ldc + col) =
                    make_float2(a[2] + b0, a[3] + b1);
            } else if (col < nsplit) {
                __half* C = (__half*)Cv;
                *(uint32_t*)(C + (size_t)row * ldc + col) =
                    packh2(a[0] * cscale, a[1] * cscale);
                *(uint32_t*)(C + (size_t)(row + 8) * ldc + col) =
                    packh2(a[2] * cscale, a[3] * cscale);
            } else {
                __half* C = (__half*)C2v;
                int c2 = col - nsplit;
                *(uint32_t*)(C + (size_t)row * ldc2 + c2)       = packh2(a[0], a[1]);
                *(uint32_t*)(C + (size_t)(row + 8) * ldc2 + c2) = packh2(a[2], a[3]);
            }
        }
    }
}

// ---------------------------------------------------------------------------
// Flash attention, fp16 mma.sync, causal. BQ=128, BK=128, 8 warps x 16 rows.
// q pre-scaled by rsqrt(128)*log2(e); exp via ex2.approx.f16x2 (produces
// packed P frags directly); row-sums via ones-MMA on the tensor pipe.
// smem: Q 32KB + 2 stages x (K 32KB + V 32KB) = 160KB.
// ---------------------------------------------------------------------------
#define ATTN_SMEM (163840 + 1024)

__global__ __launch_bounds__(256, 1)
void attn_h_kernel(const __half* __restrict__ qh, const __half* __restrict__ kvh,
                   __half* __restrict__ ctxh)
{
    extern __shared__ char smem_raw[];
    uint32_t sb = (smem_u32(smem_raw) + 1023u) & ~1023u;
    const uint32_t Qs  = sb;
    const uint32_t KB0 = sb + 32768;
    const uint32_t VB0 = sb + 65536;
    const uint32_t KB1 = sb + 98304;
    const uint32_t VB1 = sb + 131072;

    const int tid  = threadIdx.x;
    const int wq   = tid >> 5;
    const int lane = tid & 31;
    const int g    = lane >> 2;
    const int tig  = lane & 3;
    const int qb = gridDim.x - 1 - blockIdx.x;
    const int h  = blockIdx.y;
    const int b  = blockIdx.z;

    const int qrow0 = qb * 128;
    const size_t qrowg  = (size_t)b * SEQ + qrow0;
    const size_t kvrowg = (size_t)b * SEQ;

#pragma unroll
    for (int i = 0; i < 8; i++) {
        int f = tid + i * 256;
        int r = f >> 4, c = f & 15;
        CP_ASYNC16(Qs + swz256(r, c),
                   qh + (qrowg + r) * D_OUTC + h * HDIM + c * 8);
        const __half* src = kvh + (kvrowg + r) * (2 * D_OUTC) + h * HDIM + c * 8;
        CP_ASYNC16(KB0 + swz256(r, c), src);
        CP_ASYNC16(VB0 + swz256(r, c), src + D_OUTC);
    }
    CP_COMMIT();

    float ob[16][4];
#pragma unroll
    for (int nt = 0; nt < 16; nt++)
#pragma unroll
        for (int e = 0; e < 4; e++) ob[nt][e] = 0.f;
    float lacc[4] = {0.f, 0.f, 0.f, 0.f};    // row-sum accumulator (ones-MMA)
    float mA = NEG_BIG, mB = NEG_BIG;
    uint32_t qf[8][4];
    const int grA = qrow0 + wq * 16 + g;
    const int grB = grA + 8;

    const uint32_t k_rowb = ((lane >> 4) << 3) + (lane & 7);
    const uint32_t k_chb  = (lane >> 3) & 1;
    const uint32_t v_rowb = (((lane >> 3) & 1) << 3) + (lane & 7);
    const uint32_t v_chb  = lane >> 4;

    for (int kb = 0; kb <= qb; kb++) {
        __syncthreads();
        if (kb + 1 <= qb) {
            const uint32_t nK = ((kb + 1) & 1) ? KB1 : KB0;
            const uint32_t nV = ((kb + 1) & 1) ? VB1 : VB0;
#pragma unroll
            for (int i = 0; i < 8; i++) {
                int f = tid + i * 256;
                int r = f >> 4, c = f & 15;
                const __half* src = kvh + (kvrowg + (size_t)(kb + 1) * 128 + r) * (2 * D_OUTC)
                                    + h * HDIM + c * 8;
                CP_ASYNC16(nK + swz256(r, c), src);
                CP_ASYNC16(nV + swz256(r, c), src + D_OUTC);
            }
        }
        CP_COMMIT();
        CP_WAIT1();
        __syncthreads();

        if (kb == 0) {
#pragma unroll
            for (int kt = 0; kt < 8; kt++) {
                uint32_t row = wq * 16 + (lane & 15);
                uint32_t ch  = kt * 2 + (lane >> 4);
                LDSM_X4(qf[kt][0], qf[kt][1], qf[kt][2], qf[kt][3],
                        Qs + swz256(row, ch));
            }
        }

        const uint32_t Kbuf = (kb & 1) ? KB1 : KB0;
        const uint32_t Vbuf = (kb & 1) ? VB1 : VB0;

        // ---- S = Q @ K^T, pipelined LDSM ----
        float sc[16][4];
#pragma unroll
        for (int nt = 0; nt < 16; nt++)
#pragma unroll
            for (int e = 0; e < 4; e++) sc[nt][e] = 0.f;

        uint32_t kr[2][4];
        LDSM_X4(kr[0][0], kr[0][1], kr[0][2], kr[0][3],
                Kbuf + swz256(k_rowb, k_chb));
#pragma unroll
        for (int np = 0; np < 8; np++) {
#pragma unroll
            for (int kt = 0; kt < 8; kt++) {
                const int idx = np * 8 + kt;
                const int cur = idx & 1, nxt = cur ^ 1;
                if (idx < 63) {
                    const int ni = idx + 1;
                    const uint32_t nrow = (uint32_t)(ni >> 3) * 16 + k_rowb;
                    const uint32_t nch  = (uint32_t)(ni & 7) * 2 + k_chb;
                    LDSM_X4(kr[nxt][0], kr[nxt][1], kr[nxt][2], kr[nxt][3],
                            Kbuf + swz256(nrow, nch));
                }
                MMA16816(sc[2 * np],     qf[kt], kr[cur][0], kr[cur][1]);
                MMA16816(sc[2 * np + 1], qf[kt], kr[cur][2], kr[cur][3]);
            }
        }

        // causal mask (diagonal block only; scores in log2 domain)
        if (kb == qb) {
#pragma unroll
            for (int nt = 0; nt < 16; nt++) {
                int c0 = kb * 128 + nt * 8 + 2 * tig;
                if (c0     > grA) sc[nt][0] = NEG_BIG;
                if (c0 + 1 > grA) sc[nt][1] = NEG_BIG;
                if (c0     > grB) sc[nt][2] = NEG_BIG;
                if (c0 + 1 > grB) sc[nt][3] = NEG_BIG;
            }
        }

        // max reduce (fp32, quad shuffle)
        float mAn = NEG_BIG, mBn = NEG_BIG;
#pragma unroll
        for (int nt = 0; nt < 16; nt++) {
            mAn = fmaxf(mAn, fmaxf(sc[nt][0], sc[nt][1]));
            mBn = fmaxf(mBn, fmaxf(sc[nt][2], sc[nt][3]));
        }
        mAn = fmaxf(mAn, __shfl_xor_sync(0xffffffffu, mAn, 1));
        mAn = fmaxf(mAn, __shfl_xor_sync(0xffffffffu, mAn, 2));
        mBn = fmaxf(mBn, __shfl_xor_sync(0xffffffffu, mBn, 1));
        mBn = fmaxf(mBn, __shfl_xor_sync(0xffffffffu, mBn, 2));
        float mAnew = fmaxf(mA, mAn);
        float mBnew = fmaxf(mB, mBn);
        float corrA = ex2f(mA - mAnew);
        float corrB = ex2f(mB - mBnew);
        mA = mAnew; mB = mBnew;

        // rescale running row-sum + O
        lacc[0] *= corrA; lacc[1] *= corrA;
        lacc[2] *= corrB; lacc[3] *= corrB;
#pragma unroll
        for (int nt = 0; nt < 16; nt++) {
            ob[nt][0] *= corrA; ob[nt][1] *= corrA;
            ob[nt][2] *= corrB; ob[nt][3] *= corrB;
        }

        // P fragments directly via f16x2 exp (masked -> -inf -> 0)
        uint32_t pa[8][4];
#pragma unroll
        for (int kt = 0; kt < 8; kt++) {
            pa[kt][0] = h2ex2(packh2(sc[2 * kt][0] - mA,     sc[2 * kt][1] - mA));
            pa[kt][1] = h2ex2(packh2(sc[2 * kt][2] - mB,     sc[2 * kt][3] - mB));
            pa[kt][2] = h2ex2(packh2(sc[2 * kt + 1][0] - mA, sc[2 * kt + 1][1] - mA));
            pa[kt][3] = h2ex2(packh2(sc[2 * kt + 1][2] - mB, sc[2 * kt + 1][3] - mB));
        }

        // row sums on the tensor pipe: lacc += P @ ones
#pragma unroll
        for (int kt = 0; kt < 8; kt++)
            MMA16816(lacc, pa[kt], H2_ONES, H2_ONES);

        // ---- O += P @ V, pipelined LDSM_T ----
        uint32_t vr[2][4];
        LDSM_X4_T(vr[0][0], vr[0][1], vr[0][2], vr[0][3],
                  Vbuf + swz256(v_rowb, v_chb));
#pragma unroll
        for (int np = 0; np < 8; np++) {
#pragma unroll
            for (int kt = 0; kt < 8; kt++) {
                const int idx = np * 8 + kt;
                const int cur = idx & 1, nxt = cur ^ 1;
                if (idx < 63) {
                    const int ni = idx + 1;
                    const uint32_t nrow = (uint32_t)(ni & 7) * 16 + v_rowb;
                    const uint32_t nch  = (uint32_t)(ni >> 3) * 2 + v_chb;
                    LDSM_X4_T(vr[nxt][0], vr[nxt][1], vr[nxt][2], vr[nxt][3],
                              Vbuf + swz256(nrow, nch));
                }
                MMA16816(ob[2 * np],     pa[kt], vr[cur][0], vr[cur][1]);
                MMA16816(ob[2 * np + 1], pa[kt], vr[cur][2], vr[cur][3]);
            }
        }
    }

    const float invA = 1.f / lacc[0];
    const float invB = 1.f / lacc[2];
    const size_t rowA = (qrowg + wq * 16 + g) * D_OUTC + h * HDIM;
#pragma unroll
    for (int nt = 0; nt < 16; nt++) {
        int col = nt * 8 + 2 * tig;
        *(uint32_t*)(ctxh + rowA + col) =
            packh2(ob[nt][0] * invA, ob[nt][1] * invA);
        *(uint32_t*)(ctxh + rowA + 8 * D_OUTC + col) =
            packh2(ob[nt][2] * invB, ob[nt][3] * invB);
    }
}

// ---------------------------------------------------------------------------
// fp32 -> fp16 convert-copy (coalesced both sides; optional column restack)
// out[r*ldout + co + c] = in[r*C + c]
// ---------------------------------------------------------------------------
__global__ void conv_copy_h(const float* __restrict__ in,
                            __half* __restrict__ out,
                            int C, int ldout, int co, int total)
{
    int i = (blockIdx.x * 256 + threadIdx.x) * 4;
    if (i < total) {
        float4 v = *reinterpret_cast<const float4*>(in + i);
        int r = i / C, c = i - r * C;
        __half2* o = reinterpret_cast<__half2*>(out + (size_t)r * ldout + co + c);
        o[0] = __floats2half2_rn(v.x, v.y);
        o[1] = __floats2half2_rn(v.z, v.w);
    }
}

// ---------------------------------------------------------------------------
// Launch (capture slot #3 = fused projection GEMM)
// ---------------------------------------------------------------------------
extern "C" void kernel_launch(void* const* d_in, const int* in_sizes, int n_in,
                              void* d_out, int out_size)
{
    const float* x    = (const float*)d_in[0];
    const float* Wq   = (const float*)d_in[1];
    const float* Wdkv = (const float*)d_in[2];
    const float* Wukv = (const float*)d_in[3];
    const float* Wout = (const float*)d_in[4];
    const float* bout = (const float*)d_in[5];
    float* out = (float*)d_out;

    __half *xh, *qh, *lath, *kvh, *ctxh, *wqd, *wukv, *wout;
    cudaGetSymbolAddress((void**)&xh,   g_xh);
    cudaGetSymbolAddress((void**)&qh,   g_qh);
    cudaGetSymbolAddress((void**)&lath, g_lath);
    cudaGetSymbolAddress((void**)&kvh,  g_kvh);
    cudaGetSymbolAddress((void**)&ctxh, g_ctxh);
    cudaGetSymbolAddress((void**)&wqd,  g_wqd);
    cudaGetSymbolAddress((void**)&wukv, g_wukv);
    cudaGetSymbolAddress((void**)&wout, g_wout);

    cudaFuncSetAttribute(gemm_h_kernel,
                         cudaFuncAttributeMaxDynamicSharedMemorySize, GEMM_SMEM);
    cudaFuncSetAttribute(attn_h_kernel,
                         cudaFuncAttributeMaxDynamicSharedMemorySize, ATTN_SMEM);

    // #0: x -> fp16
    conv_copy_h<<<(MTOT * D_INC) / 1024, 256>>>(x, xh, D_INC, D_INC, 0, MTOT * D_INC);
    // #1, #2: Wq|Wdkv -> stacked [2048][2304] fp16 (no transpose)
    conv_copy_h<<<(D_INC * D_OUTC) / 1024, 256>>>(
        Wq, wqd, D_OUTC, D_OUTC + LATENT, 0, D_INC * D_OUTC);
    conv_copy_h<<<(D_INC * LATENT) / 1024, 256>>>(
        Wdkv, wqd, LATENT, D_OUTC + LATENT, D_OUTC, D_INC * LATENT);

    // #3: [q*scale | latent] = x @ [Wq | Wdkv]
    gemm_h_kernel<<<dim3((D_OUTC + LATENT) / 128, MTOT / 128), 256, GEMM_SMEM>>>(
        xh, wqd, nullptr, qh, D_OUTC, lath, LATENT, D_OUTC,
        D_INC, D_INC, D_OUTC + LATENT, 0, QK_SCALE);

    // #4: Wukv -> fp16 [256][4096]
    conv_copy_h<<<(LATENT * 2 * D_OUTC) / 1024, 256>>>(
        Wukv, wukv, 2 * D_OUTC, 2 * D_OUTC, 0, LATENT * 2 * D_OUTC);

    // #5: kv = latent @ Wukv
    gemm_h_kernel<<<dim3((2 * D_OUTC) / 128, MTOT / 128), 256, GEMM_SMEM>>>(
        lath, wukv, nullptr, kvh, 2 * D_OUTC, nullptr, 0, 1 << 30,
        LATENT, LATENT, 2 * D_OUTC, 0, 1.0f);

    // #6: Wout -> fp16 [2048][2048]
    conv_copy_h<<<(D_OUTC * D_INC) / 1024, 256>>>(
        Wout, wout, D_INC, D_INC, 0, D_OUTC * D_INC);

    // #7: attention -> ctx
    attn_h_kernel<<<dim3(SEQ / 128, NHEADS, BATCH), 256, ATTN_SMEM>>>(qh, kvh, ctxh);

    // #8: out = ctx @ Wout + b  (fp32)
    gemm_h_kernel<<<dim3(D_INC / 128, MTOT / 128), 256, GEMM_SMEM>>>(
        ctxh, wout, bout, out, D_INC, nullptr, 0, 1 << 30,
        D_OUTC, D_OUTC, D_INC, 1, 1.0f);
}

// round 8
// speedup vs baseline: 9.7354x; 1.1446x over previous
#include <cuda_runtime.h>
#include <cuda_fp16.h>
#include <cstdint>
#include <math.h>

// Problem constants
#define D_INC   2048
#define D_OUTC  2048
#define NHEADS  16
#define HDIM    128
#define LATENT  256
#define BATCH   2
#define SEQ     2048
#define MTOT    (BATCH * SEQ)        // 4096

#define NEG_BIG (-1.0e30f)
// rsqrt(128) * log2(e)  — folded into q projection; softmax uses ex2
#define QK_SCALE 0.12751875732f
#define H2_ONES  0x3C003C00u

// ---------------------------------------------------------------------------
// Scratch (device globals; no allocation allowed)
// ---------------------------------------------------------------------------
__device__ __align__(16) __half g_xh  [(size_t)MTOT * D_INC];
__device__ __align__(16) __half g_qh  [(size_t)MTOT * D_OUTC];
__device__ __align__(16) __half g_lath[(size_t)MTOT * LATENT];
__device__ __align__(16) __half g_kvh [(size_t)MTOT * 2 * D_OUTC];
__device__ __align__(16) __half g_ctxh[(size_t)MTOT * D_OUTC];
__device__ __align__(16) __half g_wqd [(size_t)D_INC * (D_OUTC + LATENT)];  // [2048][2304]
__device__ __align__(16) __half g_wukv[(size_t)LATENT * 2 * D_OUTC];        // [256][4096]
__device__ __align__(16) __half g_wout[(size_t)D_OUTC * D_INC];             // [2048][2048]

// ---------------------------------------------------------------------------
// PTX helpers
// ---------------------------------------------------------------------------
__device__ __forceinline__ uint32_t smem_u32(const void* p) {
    uint32_t a;
    asm("{ .reg .u64 t; cvta.to.shared.u64 t, %1; cvt.u32.u64 %0, t; }"
        : "=r"(a) : "l"(p));
    return a;
}
__device__ __forceinline__ float ex2f(float x) {
    float y;
    asm("ex2.approx.f32 %0, %1;" : "=f"(y) : "f"(x));
    return y;
}
__device__ __forceinline__ uint32_t h2ex2(uint32_t x) {
    uint32_t y;
    asm("ex2.approx.f16x2 %0, %1;" : "=r"(y) : "r"(x));
    return y;
}

#define CP_ASYNC16(dst, src) \
    asm volatile("cp.async.cg.shared.global [%0], [%1], 16;" \
                 :: "r"(dst), "l"(src) : "memory")
#define CP_COMMIT() asm volatile("cp.async.commit_group;" ::: "memory")
#define CP_WAIT1()  asm volatile("cp.async.wait_group 1;" ::: "memory")

#define LDSM_X4(r0, r1, r2, r3, a) \
    asm volatile("ldmatrix.sync.aligned.m8n8.x4.shared.b16 {%0,%1,%2,%3}, [%4];" \
                 : "=r"(r0), "=r"(r1), "=r"(r2), "=r"(r3) : "r"(a))
#define LDSM_X4_T(r0, r1, r2, r3, a) \
    asm volatile("ldmatrix.sync.aligned.m8n8.x4.trans.shared.b16 {%0,%1,%2,%3}, [%4];" \
                 : "=r"(r0), "=r"(r1), "=r"(r2), "=r"(r3) : "r"(a))

#define MMA16816(d, a, b0_, b1_) \
    asm volatile("mma.sync.aligned.m16n8k16.row.col.f32.f16.f16.f32 " \
                 "{%0,%1,%2,%3}, {%4,%5,%6,%7}, {%8,%9}, {%0,%1,%2,%3};" \
                 : "+f"((d)[0]), "+f"((d)[1]), "+f"((d)[2]), "+f"((d)[3]) \
                 : "r"((a)[0]), "r"((a)[1]), "r"((a)[2]), "r"((a)[3]), \
                   "r"(b0_), "r"(b1_))

__device__ __forceinline__ uint32_t swz128(uint32_t r, uint32_t c) {
    return r * 128u + ((c ^ (r & 7u)) << 4);
}
__device__ __forceinline__ uint32_t swz256(uint32_t r, uint32_t c) {
    return r * 256u + ((c ^ (r & 7u)) << 4);
}
__device__ __forceinline__ uint32_t packh2(float a, float b) {
    __half2 h = __floats2half2_rn(a, b);
    return *reinterpret_cast<uint32_t*>(&h);
}

// ---------------------------------------------------------------------------
// fp16 GEMM: C[M,N] = A[M,K] @ B[K,N]   (B row-major [K][N], trans-ldmatrix)
// CTA 128(M) x 128(N), BK=64, 8 warps (4M x 2N), warp tile 32x64.
// 3-stage cp.async pipeline (32KB/stage) -> 2 CTAs/SM (regs capped 128).
// mbase: M-tile offset (batch-split launches).
// ---------------------------------------------------------------------------
#define GSTAGE     32768
#define GEMM_SMEM  (3 * GSTAGE + 1024)

__device__ __forceinline__ void gemm_load_stage(
    uint32_t buf, const __half* __restrict__ A, const __half* __restrict__ B,
    int lda, int ldb, int m0, int n0, int k0, int tid)
{
    const uint32_t bufA = buf, bufB = buf + 16384;
#pragma unroll
    for (int i = 0; i < 4; i++) {            // A: 128 m-rows x 8 chunks
        int f = tid + i * 256;
        int r = f >> 3, c = f & 7;
        CP_ASYNC16(bufA + swz128(r, c),
                   A + (size_t)(m0 + r) * lda + k0 + c * 8);
    }
#pragma unroll
    for (int i = 0; i < 4; i++) {            // B: 64 k-rows x 16 chunks
        int f = tid + i * 256;
        int r = f >> 4, c = f & 15;
        CP_ASYNC16(bufB + swz256(r, c),
                   B + (size_t)(k0 + r) * ldb + n0 + c * 8);
    }
}

__global__ __launch_bounds__(256, 2)
void gemm_h_kernel(const __half* __restrict__ A, const __half* __restrict__ B,
                   const float* __restrict__ bias,
                   void* __restrict__ Cv, int ldc,
                   void* __restrict__ C2v, int ldc2, int nsplit,
                   int K, int lda, int ldb, int fp32out, float cscale, int mbase)
{
    extern __shared__ char smem_raw[];
    uint32_t sb = (smem_u32(smem_raw) + 1023u) & ~1023u;

    const int tid  = threadIdx.x;
    const int wid  = tid >> 5;
    const int lane = tid & 31;
    const int wm   = wid & 3;
    const int wn   = wid >> 2;
    const int g    = lane >> 2;
    const int tig  = lane & 3;
    const int m0 = (blockIdx.y + mbase) * 128;
    const int n0 = blockIdx.x * 128;

    float acc[2][8][4];
#pragma unroll
    for (int mt = 0; mt < 2; mt++)
#pragma unroll
        for (int nt = 0; nt < 8; nt++)
#pragma unroll
            for (int e = 0; e < 4; e++) acc[mt][nt][e] = 0.f;

    const uint32_t a_row  = wm * 32 + (lane & 15);
    const uint32_t a_chb  = lane >> 4;
    const uint32_t bt_row = (((lane >> 3) & 1) << 3) + (lane & 7);
    const uint32_t bt_chb = lane >> 4;

    const int S = K >> 6;

    gemm_load_stage(sb,          A, B, lda, ldb, m0, n0, 0,  tid); CP_COMMIT();
    gemm_load_stage(sb + GSTAGE, A, B, lda, ldb, m0, n0, 64, tid); CP_COMMIT();

    for (int s = 0; s < S; s++) {
        CP_WAIT1();
        __syncthreads();
        if (s + 2 < S) {
            int bi = s + 2 - 3 * ((s + 2) / 3);
            gemm_load_stage(sb + bi * GSTAGE,
                            A, B, lda, ldb, m0, n0, (s + 2) * 64, tid);
        }
        CP_COMMIT();

        const int sbi = s - 3 * (s / 3);
        const uint32_t bA = sb + sbi * GSTAGE;
        const uint32_t bB = bA + 16384;

#pragma unroll
        for (int kt = 0; kt < 4; kt++) {
            uint32_t af[2][4], bf[8][2];
#pragma unroll
            for (int mt = 0; mt < 2; mt++)
                LDSM_X4(af[mt][0], af[mt][1], af[mt][2], af[mt][3],
                        bA + swz128(a_row + mt * 16, kt * 2 + a_chb));
#pragma unroll
            for (int np = 0; np < 4; np++) {
                uint32_t r0, r1, r2, r3;
                LDSM_X4_T(r0, r1, r2, r3,
                          bB + swz256(kt * 16 + bt_row,
                                      (uint32_t)(wn * 8 + np * 2) + bt_chb));
                bf[2 * np][0] = r0; bf[2 * np][1] = r1;
                bf[2 * np + 1][0] = r2; bf[2 * np + 1][1] = r3;
            }
#pragma unroll
            for (int mt = 0; mt < 2; mt++)
#pragma unroll
                for (int nt = 0; nt < 8; nt++)
                    MMA16816(acc[mt][nt], af[mt], bf[nt][0], bf[nt][1]);
        }
    }

    // Epilogue
#pragma unroll
    for (int mt = 0; mt < 2; mt++) {
#pragma unroll
        for (int nt = 0; nt < 8; nt++) {
            int row = m0 + wm * 32 + mt * 16 + g;
            int col = n0 + wn * 64 + nt * 8 + 2 * tig;
            float* a = acc[mt][nt];
            if (fp32out) {
                float* C = (float*)Cv;
                float b0 = bias ? bias[col]     : 0.f;
                float b1 = bias ? bias[col + 1] : 0.f;
                *(float2*)(C + (size_t)row * ldc + col) =
                    make_float2(a[0] + b0, a[1] + b1);
                *(float2*)(C + (size_t)(row + 8) * ldc + col) =
                    make_float2(a[2] + b0, a[3] + b1);
            } else if (col < nsplit) {
                __half* C = (__half*)Cv;
                *(uint32_t*)(C + (size_t)row * ldc + col) =
                    packh2(a[0] * cscale, a[1] * cscale);
                *(uint32_t*)(C + (size_t)(row + 8) * ldc + col) =
                    packh2(a[2] * cscale, a[3] * cscale);
            } else {
                __half* C = (__half*)C2v;
                int c2 = col - nsplit;
                *(uint32_t*)(C + (size_t)row * ldc2 + c2)       = packh2(a[0], a[1]);
                *(uint32_t*)(C + (size_t)(row + 8) * ldc2 + c2) = packh2(a[2], a[3]);
            }
        }
    }
}

// ---------------------------------------------------------------------------
// Flash attention, fp16 mma.sync, causal. BQ=128, BK=128, 8 warps x 16 rows.
// bsel: batch index (batch-split launches).
// ---------------------------------------------------------------------------
#define ATTN_SMEM (163840 + 1024)

__global__ __launch_bounds__(256, 1)
void attn_h_kernel(const __half* __restrict__ qh, const __half* __restrict__ kvh,
                   __half* __restrict__ ctxh, int bsel)
{
    extern __shared__ char smem_raw[];
    uint32_t sb = (smem_u32(smem_raw) + 1023u) & ~1023u;
    const uint32_t Qs  = sb;
    const uint32_t KB0 = sb + 32768;
    const uint32_t VB0 = sb + 65536;
    const uint32_t KB1 = sb + 98304;
    const uint32_t VB1 = sb + 131072;

    const int tid  = threadIdx.x;
    const int wq   = tid >> 5;
    const int lane = tid & 31;
    const int g    = lane >> 2;
    const int tig  = lane & 3;
    const int qb = gridDim.x - 1 - blockIdx.x;
    const int h  = blockIdx.y;
    const int b  = bsel;

    const int qrow0 = qb * 128;
    const size_t qrowg  = (size_t)b * SEQ + qrow0;
    const size_t kvrowg = (size_t)b * SEQ;

#pragma unroll
    for (int i = 0; i < 8; i++) {
        int f = tid + i * 256;
        int r = f >> 4, c = f & 15;
        CP_ASYNC16(Qs + swz256(r, c),
                   qh + (qrowg + r) * D_OUTC + h * HDIM + c * 8);
        const __half* src = kvh + (kvrowg + r) * (2 * D_OUTC) + h * HDIM + c * 8;
        CP_ASYNC16(KB0 + swz256(r, c), src);
        CP_ASYNC16(VB0 + swz256(r, c), src + D_OUTC);
    }
    CP_COMMIT();

    float ob[16][4];
#pragma unroll
    for (int nt = 0; nt < 16; nt++)
#pragma unroll
        for (int e = 0; e < 4; e++) ob[nt][e] = 0.f;
    float lacc[4] = {0.f, 0.f, 0.f, 0.f};
    float mA = NEG_BIG, mB = NEG_BIG;
    uint32_t qf[8][4];
    const int grA = qrow0 + wq * 16 + g;
    const int grB = grA + 8;

    const uint32_t k_rowb = ((lane >> 4) << 3) + (lane & 7);
    const uint32_t k_chb  = (lane >> 3) & 1;
    const uint32_t v_rowb = (((lane >> 3) & 1) << 3) + (lane & 7);
    const uint32_t v_chb  = lane >> 4;

    for (int kb = 0; kb <= qb; kb++) {
        __syncthreads();
        if (kb + 1 <= qb) {
            const uint32_t nK = ((kb + 1) & 1) ? KB1 : KB0;
            const uint32_t nV = ((kb + 1) & 1) ? VB1 : VB0;
#pragma unroll
            for (int i = 0; i < 8; i++) {
                int f = tid + i * 256;
                int r = f >> 4, c = f & 15;
                const __half* src = kvh + (kvrowg + (size_t)(kb + 1) * 128 + r) * (2 * D_OUTC)
                                    + h * HDIM + c * 8;
                CP_ASYNC16(nK + swz256(r, c), src);
                CP_ASYNC16(nV + swz256(r, c), src + D_OUTC);
            }
        }
        CP_COMMIT();
        CP_WAIT1();
        __syncthreads();

        if (kb == 0) {
#pragma unroll
            for (int kt = 0; kt < 8; kt++) {
                uint32_t row = wq * 16 + (lane & 15);
                uint32_t ch  = kt * 2 + (lane >> 4);
                LDSM_X4(qf[kt][0], qf[kt][1], qf[kt][2], qf[kt][3],
                        Qs + swz256(row, ch));
            }
        }

        const uint32_t Kbuf = (kb & 1) ? KB1 : KB0;
        const uint32_t Vbuf = (kb & 1) ? VB1 : VB0;

        // ---- S = Q @ K^T, pipelined LDSM ----
        float sc[16][4];
#pragma unroll
        for (int nt = 0; nt < 16; nt++)
#pragma unroll
            for (int e = 0; e < 4; e++) sc[nt][e] = 0.f;

        uint32_t kr[2][4];
        LDSM_X4(kr[0][0], kr[0][1], kr[0][2], kr[0][3],
                Kbuf + swz256(k_rowb, k_chb));
#pragma unroll
        for (int np = 0; np < 8; np++) {
#pragma unroll
            for (int kt = 0; kt < 8; kt++) {
                const int idx = np * 8 + kt;
                const int cur = idx & 1, nxt = cur ^ 1;
                if (idx < 63) {
                    const int ni = idx + 1;
                    const uint32_t nrow = (uint32_t)(ni >> 3) * 16 + k_rowb;
                    const uint32_t nch  = (uint32_t)(ni & 7) * 2 + k_chb;
                    LDSM_X4(kr[nxt][0], kr[nxt][1], kr[nxt][2], kr[nxt][3],
                            Kbuf + swz256(nrow, nch));
                }
                MMA16816(sc[2 * np],     qf[kt], kr[cur][0], kr[cur][1]);
                MMA16816(sc[2 * np + 1], qf[kt], kr[cur][2], kr[cur][3]);
            }
        }

        if (kb == qb) {
#pragma unroll
            for (int nt = 0; nt < 16; nt++) {
                int c0 = kb * 128 + nt * 8 + 2 * tig;
                if (c0     > grA) sc[nt][0] = NEG_BIG;
                if (c0 + 1 > grA) sc[nt][1] = NEG_BIG;
                if (c0     > grB) sc[nt][2] = NEG_BIG;
                if (c0 + 1 > grB) sc[nt][3] = NEG_BIG;
            }
        }

        float mAn = NEG_BIG, mBn = NEG_BIG;
#pragma unroll
        for (int nt = 0; nt < 16; nt++) {
            mAn = fmaxf(mAn, fmaxf(sc[nt][0], sc[nt][1]));
            mBn = fmaxf(mBn, fmaxf(sc[nt][2], sc[nt][3]));
        }
        mAn = fmaxf(mAn, __shfl_xor_sync(0xffffffffu, mAn, 1));
        mAn = fmaxf(mAn, __shfl_xor_sync(0xffffffffu, mAn, 2));
        mBn = fmaxf(mBn, __shfl_xor_sync(0xffffffffu, mBn, 1));
        mBn = fmaxf(mBn, __shfl_xor_sync(0xffffffffu, mBn, 2));
        float mAnew = fmaxf(mA, mAn);
        float mBnew = fmaxf(mB, mBn);
        float corrA = ex2f(mA - mAnew);
        float corrB = ex2f(mB - mBnew);
        mA = mAnew; mB = mBnew;

        lacc[0] *= corrA; lacc[1] *= corrA;
        lacc[2] *= corrB; lacc[3] *= corrB;
#pragma unroll
        for (int nt = 0; nt < 16; nt++) {
            ob[nt][0] *= corrA; ob[nt][1] *= corrA;
            ob[nt][2] *= corrB; ob[nt][3] *= corrB;
        }

        uint32_t pa[8][4];
#pragma unroll
        for (int kt = 0; kt < 8; kt++) {
            pa[kt][0] = h2ex2(packh2(sc[2 * kt][0] - mA,     sc[2 * kt][1] - mA));
            pa[kt][1] = h2ex2(packh2(sc[2 * kt][2] - mB,     sc[2 * kt][3] - mB));
            pa[kt][2] = h2ex2(packh2(sc[2 * kt + 1][0] - mA, sc[2 * kt + 1][1] - mA));
            pa[kt][3] = h2ex2(packh2(sc[2 * kt + 1][2] - mB, sc[2 * kt + 1][3] - mB));
        }

#pragma unroll
        for (int kt = 0; kt < 8; kt++)
            MMA16816(lacc, pa[kt], H2_ONES, H2_ONES);

        // ---- O += P @ V, pipelined LDSM_T ----
        uint32_t vr[2][4];
        LDSM_X4_T(vr[0][0], vr[0][1], vr[0][2], vr[0][3],
                  Vbuf + swz256(v_rowb, v_chb));
#pragma unroll
        for (int np = 0; np < 8; np++) {
#pragma unroll
            for (int kt = 0; kt < 8; kt++) {
                const int idx = np * 8 + kt;
                const int cur = idx & 1, nxt = cur ^ 1;
                if (idx < 63) {
                    const int ni = idx + 1;
                    const uint32_t nrow = (uint32_t)(ni & 7) * 16 + v_rowb;
                    const uint32_t nch  = (uint32_t)(ni >> 3) * 2 + v_chb;
                    LDSM_X4_T(vr[nxt][0], vr[nxt][1], vr[nxt][2], vr[nxt][3],
                              Vbuf + swz256(nrow, nch));
                }
                MMA16816(ob[2 * np],     pa[kt], vr[cur][0], vr[cur][1]);
                MMA16816(ob[2 * np + 1], pa[kt], vr[cur][2], vr[cur][3]);
            }
        }
    }

    const float invA = 1.f / lacc[0];
    const float invB = 1.f / lacc[2];
    const size_t rowA = (qrowg + wq * 16 + g) * D_OUTC + h * HDIM;
#pragma unroll
    for (int nt = 0; nt < 16; nt++) {
        int col = nt * 8 + 2 * tig;
        *(uint32_t*)(ctxh + rowA + col) =
            packh2(ob[nt][0] * invA, ob[nt][1] * invA);
        *(uint32_t*)(ctxh + rowA + 8 * D_OUTC + col) =
            packh2(ob[nt][2] * invB, ob[nt][3] * invB);
    }
}

// ---------------------------------------------------------------------------
// fp32 -> fp16 convert-copy (coalesced; optional column restack)
// ---------------------------------------------------------------------------
__global__ void conv_copy_h(const float* __restrict__ in,
                            __half* __restrict__ out,
                            int C, int ldout, int co, int total)
{
    int i = (blockIdx.x * 256 + threadIdx.x) * 4;
    if (i < total) {
        float4 v = *reinterpret_cast<const float4*>(in + i);
        int r = i / C, c = i - r * C;
        __half2* o = reinterpret_cast<__half2*>(out + (size_t)r * ldout + co + c);
        o[0] = __floats2half2_rn(v.x, v.y);
        o[1] = __floats2half2_rn(v.z, v.w);
    }
}

// ---------------------------------------------------------------------------
// Launch: two per-batch dependency chains on two streams (graph fork/join)
// ---------------------------------------------------------------------------
extern "C" void kernel_launch(void* const* d_in, const int* in_sizes, int n_in,
                              void* d_out, int out_size)
{
    const float* x    = (const float*)d_in[0];
    const float* Wq   = (const float*)d_in[1];
    const float* Wdkv = (const float*)d_in[2];
    const float* Wukv = (const float*)d_in[3];
    const float* Wout = (const float*)d_in[4];
    const float* bout = (const float*)d_in[5];
    float* out = (float*)d_out;

    __half *xh, *qh, *lath, *kvh, *ctxh, *wqd, *wukv, *wout;
    cudaGetSymbolAddress((void**)&xh,   g_xh);
    cudaGetSymbolAddress((void**)&qh,   g_qh);
    cudaGetSymbolAddress((void**)&lath, g_lath);
    cudaGetSymbolAddress((void**)&kvh,  g_kvh);
    cudaGetSymbolAddress((void**)&ctxh, g_ctxh);
    cudaGetSymbolAddress((void**)&wqd,  g_wqd);
    cudaGetSymbolAddress((void**)&wukv, g_wukv);
    cudaGetSymbolAddress((void**)&wout, g_wout);

    static cudaStream_t s1 = nullptr, s2 = nullptr;
    static cudaEvent_t e0, e_wqd, e_ukv, e_out, e_d1, e_d2;
    if (!s1) {
        cudaStreamCreateWithFlags(&s1, cudaStreamNonBlocking);
        cudaStreamCreateWithFlags(&s2, cudaStreamNonBlocking);
        cudaEventCreateWithFlags(&e0,    cudaEventDisableTiming);
        cudaEventCreateWithFlags(&e_wqd, cudaEventDisableTiming);
        cudaEventCreateWithFlags(&e_ukv, cudaEventDisableTiming);
        cudaEventCreateWithFlags(&e_out, cudaEventDisableTiming);
        cudaEventCreateWithFlags(&e_d1,  cudaEventDisableTiming);
        cudaEventCreateWithFlags(&e_d2,  cudaEventDisableTiming);
        cudaFuncSetAttribute(gemm_h_kernel,
                             cudaFuncAttributeMaxDynamicSharedMemorySize, GEMM_SMEM);
        cudaFuncSetAttribute(attn_h_kernel,
                             cudaFuncAttributeMaxDynamicSharedMemorySize, ATTN_SMEM);
    }

    const int HM = MTOT / 2;                 // rows per batch = 2048
    const int HE = HM * D_INC;               // x elements per batch

    // Fork both streams off the capture (null) stream
    cudaEventRecord(e0, 0);
    cudaStreamWaitEvent(s1, e0, 0);
    cudaStreamWaitEvent(s2, e0, 0);

    // ---- S1: weights for proj, then batch-0 chain ----
    conv_copy_h<<<(D_INC * D_OUTC) / 1024, 256, 0, s1>>>(
        Wq, wqd, D_OUTC, D_OUTC + LATENT, 0, D_INC * D_OUTC);
    conv_copy_h<<<(D_INC * LATENT) / 1024, 256, 0, s1>>>(
        Wdkv, wqd, LATENT, D_OUTC + LATENT, D_OUTC, D_INC * LATENT);
    cudaEventRecord(e_wqd, s1);
    conv_copy_h<<<HE / 1024, 256, 0, s1>>>(x, xh, D_INC, D_INC, 0, HE);

    // ---- S2: batch-1 x conv + other weights ----
    conv_copy_h<<<HE / 1024, 256, 0, s2>>>(x + HE, xh + HE, D_INC, D_INC, 0, HE);
    conv_copy_h<<<(LATENT * 2 * D_OUTC) / 1024, 256, 0, s2>>>(
        Wukv, wukv, 2 * D_OUTC, 2 * D_OUTC, 0, LATENT * 2 * D_OUTC);
    cudaEventRecord(e_ukv, s2);
    conv_copy_h<<<(D_OUTC * D_INC) / 1024, 256, 0, s2>>>(
        Wout, wout, D_INC, D_INC, 0, D_OUTC * D_INC);
    cudaEventRecord(e_out, s2);

    // ---- S1 chain (batch 0) ----
    gemm_h_kernel<<<dim3((D_OUTC + LATENT) / 128, HM / 128), 256, GEMM_SMEM, s1>>>(
        xh, wqd, nullptr, qh, D_OUTC, lath, LATENT, D_OUTC,
        D_INC, D_INC, D_OUTC + LATENT, 0, QK_SCALE, 0);
    cudaStreamWaitEvent(s1, e_ukv, 0);
    gemm_h_kernel<<<dim3((2 * D_OUTC) / 128, HM / 128), 256, GEMM_SMEM, s1>>>(
        lath, wukv, nullptr, kvh, 2 * D_OUTC, nullptr, 0, 1 << 30,
        LATENT, LATENT, 2 * D_OUTC, 0, 1.0f, 0);
    attn_h_kernel<<<dim3(SEQ / 128, NHEADS, 1), 256, ATTN_SMEM, s1>>>(qh, kvh, ctxh, 0);
    cudaStreamWaitEvent(s1, e_out, 0);
    gemm_h_kernel<<<dim3(D_INC / 128, HM / 128), 256, GEMM_SMEM, s1>>>(
        ctxh, wout, bout, out, D_INC, nullptr, 0, 1 << 30,
        D_OUTC, D_OUTC, D_INC, 1, 1.0f, 0);
    cudaEventRecord(e_d1, s1);

    // ---- S2 chain (batch 1) ----
    cudaStreamWaitEvent(s2, e_wqd, 0);
    gemm_h_kernel<<<dim3((D_OUTC + LATENT) / 128, HM / 128), 256, GEMM_SMEM, s2>>>(
        xh, wqd, nullptr, qh, D_OUTC, lath, LATENT, D_OUTC,
        D_INC, D_INC, D_OUTC + LATENT, 0, QK_SCALE, HM / 128);
    gemm_h_kernel<<<dim3((2 * D_OUTC) / 128, HM / 128), 256, GEMM_SMEM, s2>>>(
        lath, wukv, nullptr, kvh, 2 * D_OUTC, nullptr, 0, 1 << 30,
        LATENT, LATENT, 2 * D_OUTC, 0, 1.0f, HM / 128);
    attn_h_kernel<<<dim3(SEQ / 128, NHEADS, 1), 256, ATTN_SMEM, s2>>>(qh, kvh, ctxh, 1);
    gemm_h_kernel<<<dim3(D_INC / 128, HM / 128), 256, GEMM_SMEM, s2>>>(
        ctxh, wout, bout, out, D_INC, nullptr, 0, 1 << 30,
        D_OUTC, D_OUTC, D_INC, 1, 1.0f, HM / 128);
    cudaEventRecord(e_d2, s2);

    // Join back into the capture stream
    cudaStreamWaitEvent(0, e_d1, 0);
    cudaStreamWaitEvent(0, e_d2, 0);
}